// round 8
// baseline (speedup 1.0000x reference)
#include <cuda_runtime.h>
#include <cuda_bf16.h>
#include <cstdint>

#define BB 8
#define SS 4096
#define TT 512
#define HH 768

// ---------------------------------------------------------------------------
// Scratch (device .bss). Split bf16 operands: [R, 2C], hi in [0,C), lo in [C,2C).
// ---------------------------------------------------------------------------
__device__ __align__(16) __nv_bfloat16 g_seq2 [(size_t)BB * SS * 2 * HH];
__device__ __align__(16) __nv_bfloat16 g_tgt2 [(size_t)BB * TT * 2 * HH];
__device__ __align__(16) __nv_bfloat16 g_W2   [(size_t)HH * 2 * HH];
__device__ __align__(16) __nv_bfloat16 g_seqt2[(size_t)BB * SS * 2 * HH];
__device__ __align__(16) __nv_bfloat16 g_tgtt2[(size_t)BB * TT * 2 * HH];
__device__ __align__(16) float         g_logits[(size_t)BB * SS * TT];
__device__ __align__(16) __nv_bfloat16 g_probs2[(size_t)BB * SS * 2 * TT];
__device__ __align__(16) __nv_bfloat16 g_vT2  [(size_t)BB * HH * 2 * TT];  // [B, H, 2T]

// ---------------------------------------------------------------------------
// Helpers (baseline PTX: cp.async / ldmatrix / mma.sync — sm_80+ ISA)
// ---------------------------------------------------------------------------
__device__ __forceinline__ uint32_t smem_u32(const void* p) {
    uint32_t a;
    asm("{ .reg .u64 t; cvta.to.shared.u64 t, %1; cvt.u32.u64 %0, t; }" : "=r"(a) : "l"(p));
    return a;
}
__device__ __forceinline__ void cp16(uint32_t saddr, const void* g) {
    asm volatile("cp.async.cg.shared.global [%0], [%1], 16;" :: "r"(saddr), "l"(g) : "memory");
}
#define CP_COMMIT() asm volatile("cp.async.commit_group;" ::: "memory")
template <int N>
__device__ __forceinline__ void cp_wait() {
    asm volatile("cp.async.wait_group %0;" :: "n"(N) : "memory");
}
__device__ __forceinline__ void ldsm_x4(uint32_t* r, uint32_t addr) {
    asm volatile("ldmatrix.sync.aligned.m8n8.x4.shared.b16 {%0,%1,%2,%3}, [%4];"
        : "=r"(r[0]), "=r"(r[1]), "=r"(r[2]), "=r"(r[3]) : "r"(addr));
}
__device__ __forceinline__ void mma_bf16(float* c, const uint32_t* a, const uint32_t* b) {
    asm volatile(
        "mma.sync.aligned.m16n8k16.row.col.f32.bf16.bf16.f32 "
        "{%0,%1,%2,%3}, {%4,%5,%6,%7}, {%8,%9}, {%0,%1,%2,%3};"
        : "+f"(c[0]), "+f"(c[1]), "+f"(c[2]), "+f"(c[3])
        : "r"(a[0]), "r"(a[1]), "r"(a[2]), "r"(a[3]), "r"(b[0]), "r"(b[1]));
}
__device__ __forceinline__ void split1(float x, __nv_bfloat16& h, __nv_bfloat16& l) {
    h = __float2bfloat16(x);
    l = __float2bfloat16(x - __bfloat162float(h));
}

// ---------------------------------------------------------------------------
// HMMA GEMM: D = Ahi*Bhi + Alo*Bhi + Ahi*Blo (split-bf16 3-term).
// A: [rows, 2C] split bf16 K-major. B: [N, 2C] split bf16 K-major.
// CTA tile 128x128, BK=64, 3-buffer cp.async, one barrier per iteration:
//   wait(stage it) -> barrier -> prefetch(it+2) -> compute(it)
// The barrier proves stage it-1 reads are done, and buffer (it+2)%3 ==
// (it-1)%3, so the early prefetch is race-free and gets ~2 iterations of
// compute to hide DRAM latency.
// 256 threads = 8 warps (2m x 4n), warp tile 64x32. smem 96KB.
// __launch_bounds__(256, 2) hard-caps 128 regs/thread -> 2 CTAs/SM guaranteed.
// EPI: 0 = relu + split-bf16; 1 = fp32; 2 = attn/cat.
// ---------------------------------------------------------------------------
template <int EPI>
__launch_bounds__(256, 2)
__global__ void gemm_mma(const __nv_bfloat16* __restrict__ A,
                         const __nv_bfloat16* __restrict__ Bm,
                         long aBatch, long bBatch, int C,
                         float* __restrict__ out0, float* __restrict__ out1,
                         __nv_bfloat16* __restrict__ obf,
                         const int* __restrict__ smask, int writeAttn)
{
    extern __shared__ char smem[];
    const uint32_t sb = smem_u32(smem);

    const int tid = threadIdx.x;
    const int wid = tid >> 5;
    const int lane = tid & 31;

    const int z = blockIdx.z;
    const int m0 = blockIdx.y * 128;
    const int n0 = blockIdx.x * 128;
    const long Kr = 2L * C;
    const __nv_bfloat16* Ab = A + (long)z * aBatch;
    const __nv_bfloat16* Bb = Bm + (long)z * bBatch;

    const int kc = C >> 6;     // 64-col chunks per segment
    const int nk = 3 * kc;

    const int vr0 = tid >> 3;          // load row base (stride 32)
    const int vc16 = (tid & 7) * 16;   // byte offset in 128B row

#define LDG_STAGE(IT, S)                                                          \
    {                                                                             \
        int _it = (IT);                                                           \
        int _seg = (_it >= 2 * kc) ? 2 : ((_it >= kc) ? 1 : 0);                   \
        int _kl = _it - _seg * kc;                                                \
        long _aC = ((_seg == 1) ? C : 0) + (long)_kl * 64 + (vc16 >> 1);          \
        long _bC = ((_seg == 2) ? C : 0) + (long)_kl * 64 + (vc16 >> 1);          \
        uint32_t _sA = sb + (S) * 32768u;                                         \
        uint32_t _sB = _sA + 16384u;                                              \
        _Pragma("unroll")                                                         \
        for (int i = 0; i < 4; i++) {                                             \
            int r = vr0 + 32 * i;                                                 \
            uint32_t sw = (uint32_t)(r * 128 + (vc16 ^ ((r & 7) << 4)));          \
            cp16(_sA + sw, Ab + (long)(m0 + r) * Kr + _aC);                       \
            cp16(_sB + sw, Bb + (long)(n0 + r) * Kr + _bC);                       \
        }                                                                         \
    }

    // prologue: prefetch stages 0,1 into buffers 0,1 (buffer 2 free)
    LDG_STAGE(0, 0); CP_COMMIT();
    LDG_STAGE(1, 1); CP_COMMIT();

    const int wm = wid & 1;     // 0..1 -> 64 rows
    const int wn = wid >> 1;    // 0..3 -> 32 cols

    float acc[4][4][4] = {};

    const int arow = wm * 64 + (lane & 15);                     // + mt*16
    const int akb = (lane >> 4) * 16;
    const int brow = wn * 32 + (lane & 7) + ((lane >> 4) * 8);  // + ntp*16
    const int bkb = ((lane >> 3) & 1) * 16;

    for (int it = 0; it < nk; it++) {
        // Stage `it` landed when at most 1 younger group (stage it+1) is
        // still pending; on the last iteration nothing younger is in flight.
        if (it + 1 < nk) cp_wait<1>(); else cp_wait<0>();
        __syncthreads();   // all warps done reading stage it-1

        // Early prefetch: buffer (it+2)%3 == (it-1)%3, proven free by the
        // barrier above. Issuing before compute gives the loads ~2 full
        // iterations of compute to hide DRAM latency.
        if (it + 2 < nk) { LDG_STAGE(it + 2, (it + 2) % 3); CP_COMMIT(); }

        const uint32_t stA = sb + (uint32_t)(it % 3) * 32768u;
        const uint32_t stB = stA + 16384u;

        #pragma unroll
        for (int ks = 0; ks < 4; ks++) {
            uint32_t afr[4][4], bfr[2][4];
            #pragma unroll
            for (int mt = 0; mt < 4; mt++) {
                const int row = arow + mt * 16;
                ldsm_x4(afr[mt], stA + row * 128 + ((ks * 32 + akb) ^ ((row & 7) << 4)));
            }
            #pragma unroll
            for (int ntp = 0; ntp < 2; ntp++) {
                const int row = brow + ntp * 16;
                ldsm_x4(bfr[ntp], stB + row * 128 + ((ks * 32 + bkb) ^ ((row & 7) << 4)));
            }
            #pragma unroll
            for (int mt = 0; mt < 4; mt++)
                #pragma unroll
                for (int nt = 0; nt < 4; nt++)
                    mma_bf16(acc[mt][nt], afr[mt], &bfr[nt >> 1][(nt & 1) * 2]);
        }
    }

    // ---- epilogue ----
    const int er = wm * 64 + (lane >> 2);        // + mt*16 (+8 for c2/c3)
    const int ec = wn * 32 + (lane & 3) * 2;     // + nt*8

    if (EPI == 0) {
        const int Nout = gridDim.x * 128;
        #pragma unroll
        for (int mt = 0; mt < 4; mt++)
            #pragma unroll
            for (int nt = 0; nt < 4; nt++)
                #pragma unroll
                for (int h = 0; h < 2; h++) {
                    const int row = m0 + er + mt * 16 + h * 8;
                    const int col = n0 + ec + nt * 8;
                    float x0 = fmaxf(acc[mt][nt][2 * h], 0.f);
                    float x1 = fmaxf(acc[mt][nt][2 * h + 1], 0.f);
                    __nv_bfloat16 h0, l0, h1, l1;
                    split1(x0, h0, l0); split1(x1, h1, l1);
                    __nv_bfloat16* oh = obf + (long)row * 2 * Nout + col;
                    *reinterpret_cast<__nv_bfloat162*>(oh) = __nv_bfloat162(h0, h1);
                    *reinterpret_cast<__nv_bfloat162*>(oh + Nout) = __nv_bfloat162(l0, l1);
                }
    } else if (EPI == 1) {
        #pragma unroll
        for (int mt = 0; mt < 4; mt++)
            #pragma unroll
            for (int nt = 0; nt < 4; nt++)
                #pragma unroll
                for (int h = 0; h < 2; h++) {
                    const int row = m0 + er + mt * 16 + h * 8;
                    const int col = n0 + ec + nt * 8;
                    float2 v = make_float2(acc[mt][nt][2 * h], acc[mt][nt][2 * h + 1]);
                    *reinterpret_cast<float2*>(out0 + ((long)z * SS + row) * TT + col) = v;
                }
    } else {
        #pragma unroll
        for (int mt = 0; mt < 4; mt++)
            #pragma unroll
            for (int nt = 0; nt < 4; nt++)
                #pragma unroll
                for (int h = 0; h < 2; h++) {
                    const int row = m0 + er + mt * 16 + h * 8;
                    const int col = n0 + ec + nt * 8;
                    const long gs = (long)z * SS + row;
                    const float m = (float)smask[gs];
                    float2 v = make_float2(acc[mt][nt][2 * h], acc[mt][nt][2 * h + 1]);
                    if (writeAttn)
                        *reinterpret_cast<float2*>(out1 + gs * (long)HH + col) = v;
                    float2 vm = make_float2(v.x * m, v.y * m);
                    *reinterpret_cast<float2*>(out0 + gs * (long)(2 * HH) + HH + col) = vm;
                }
    }
#undef LDG_STAGE
}

// ---------------------------------------------------------------------------
// fp32 [R,C] (row-masked) -> split bf16 [R,2C]; optionally also writes the
// masked fp32 row into out_cat[row, 0:C] (cat first half, stride 2C).
// ---------------------------------------------------------------------------
__launch_bounds__(256)
__global__ void split_mask(const float* __restrict__ in, const int* __restrict__ mask,
                           __nv_bfloat16* __restrict__ out, float* __restrict__ cat,
                           int R, int C)
{
    const long idx = (long)blockIdx.x * blockDim.x + threadIdx.x;  // float4 units
    const long total = (long)R * C / 4;
    if (idx >= total) return;
    const long row = idx / (C / 4);
    const int c4 = (int)(idx % (C / 4));
    const float m = mask ? (float)mask[row] : 1.0f;
    float4 v = reinterpret_cast<const float4*>(in)[idx];
    v.x *= m; v.y *= m; v.z *= m; v.w *= m;
    __nv_bfloat16 h0, l0, h1, l1, h2, l2, h3, l3;
    split1(v.x, h0, l0); split1(v.y, h1, l1); split1(v.z, h2, l2); split1(v.w, h3, l3);
    __nv_bfloat16* oh = out + row * 2L * C + c4 * 4;
    __nv_bfloat16* ol = oh + C;
    reinterpret_cast<__nv_bfloat162*>(oh)[0] = __nv_bfloat162(h0, h1);
    reinterpret_cast<__nv_bfloat162*>(oh)[1] = __nv_bfloat162(h2, h3);
    reinterpret_cast<__nv_bfloat162*>(ol)[0] = __nv_bfloat162(l0, l1);
    reinterpret_cast<__nv_bfloat162*>(ol)[1] = __nv_bfloat162(l2, l3);
    if (cat)
        reinterpret_cast<float4*>(cat)[row * (long)(2 * C / 4) + c4] = v;
}

// ---------------------------------------------------------------------------
// V^T split: O[b,h,t] = split(V[b,t,h]);  O layout [B, H, 2T]
// ---------------------------------------------------------------------------
__global__ void vT_split(const float* __restrict__ V, __nv_bfloat16* __restrict__ O)
{
    __shared__ float tile[32][33];
    const int b = blockIdx.z;
    const int t0 = blockIdx.x * 32, h0 = blockIdx.y * 32;
    const int tx = threadIdx.x, ty = threadIdx.y;  // 32 x 8
    #pragma unroll
    for (int i = 0; i < 32; i += 8)
        tile[ty + i][tx] = V[((long)b * TT + t0 + ty + i) * HH + h0 + tx];
    __syncthreads();
    #pragma unroll
    for (int i = 0; i < 32; i += 8) {
        const int h = h0 + ty + i, t = t0 + tx;
        __nv_bfloat16 hh, ll;
        split1(tile[tx][ty + i], hh, ll);
        const long base = ((long)b * HH + h) * (2L * TT) + t;
        O[base] = hh; O[base + TT] = ll;
    }
}

// ---------------------------------------------------------------------------
// Row softmax over T=512 + split-bf16 probs write.
// ---------------------------------------------------------------------------
__launch_bounds__(128)
__global__ void softmax_split(const float* __restrict__ logits, __nv_bfloat16* __restrict__ P2)
{
    const long row = blockIdx.x;
    const float* p = logits + row * TT;
    const int tid = threadIdx.x;
    const int warp = tid >> 5, lane = tid & 31;

    float v[4];
    #pragma unroll
    for (int i = 0; i < 4; i++) v[i] = p[tid + 128 * i];

    float mx = fmaxf(fmaxf(v[0], v[1]), fmaxf(v[2], v[3]));
    #pragma unroll
    for (int o = 16; o > 0; o >>= 1) mx = fmaxf(mx, __shfl_xor_sync(0xffffffffu, mx, o));
    __shared__ float smx[4];
    if (lane == 0) smx[warp] = mx;
    __syncthreads();
    mx = fmaxf(fmaxf(smx[0], smx[1]), fmaxf(smx[2], smx[3]));

    float sum = 0.f;
    #pragma unroll
    for (int i = 0; i < 4; i++) { v[i] = __expf(v[i] - mx); sum += v[i]; }
    #pragma unroll
    for (int o = 16; o > 0; o >>= 1) sum += __shfl_xor_sync(0xffffffffu, sum, o);
    __shared__ float ssum[4];
    if (lane == 0) ssum[warp] = sum;
    __syncthreads();
    const float inv = 1.0f / (ssum[0] + ssum[1] + ssum[2] + ssum[3]);

    __nv_bfloat16* out = P2 + row * 2L * TT;
    #pragma unroll
    for (int i = 0; i < 4; i++) {
        const int idx = tid + 128 * i;
        __nv_bfloat16 h, l;
        split1(v[i] * inv, h, l);
        out[idx] = h; out[TT + idx] = l;
    }
}

// ---------------------------------------------------------------------------

extern "C" void kernel_launch(void* const* d_in, const int* in_sizes, int n_in,
                              void* d_out, int out_size)
{
    const float* seq   = (const float*)d_in[0];
    const int*   smask = (const int*)d_in[1];
    const float* tgt   = (const float*)d_in[2];
    const int*   tmask = (const int*)d_in[3];
    const float* W     = (const float*)d_in[4];
    float* out = (float*)d_out;

    __nv_bfloat16 *p_seq2, *p_tgt2, *p_W2, *p_seqt2, *p_tgtt2, *p_probs2, *p_vT2;
    float* p_logits;
    cudaGetSymbolAddress((void**)&p_seq2, g_seq2);
    cudaGetSymbolAddress((void**)&p_tgt2, g_tgt2);
    cudaGetSymbolAddress((void**)&p_W2, g_W2);
    cudaGetSymbolAddress((void**)&p_seqt2, g_seqt2);
    cudaGetSymbolAddress((void**)&p_tgtt2, g_tgtt2);
    cudaGetSymbolAddress((void**)&p_logits, g_logits);
    cudaGetSymbolAddress((void**)&p_probs2, g_probs2);
    cudaGetSymbolAddress((void**)&p_vT2, g_vT2);

    const int write_attn = (out_size >= BB * SS * 3 * HH) ? 1 : 0;
    float* out_attn = out + (size_t)BB * SS * 2 * HH;

    const int SMEM_DYN = 3 * 32768;  // 98304 -> 2 CTAs/SM
    cudaFuncSetAttribute(gemm_mma<0>, cudaFuncAttributeMaxDynamicSharedMemorySize, SMEM_DYN);
    cudaFuncSetAttribute(gemm_mma<1>, cudaFuncAttributeMaxDynamicSharedMemorySize, SMEM_DYN);
    cudaFuncSetAttribute(gemm_mma<2>, cudaFuncAttributeMaxDynamicSharedMemorySize, SMEM_DYN);

    // 0) operand conversions (seq variant also writes cat first half)
    split_mask<<<(BB * SS * HH / 4 + 255) / 256, 256>>>(seq, smask, p_seq2, out, BB * SS, HH);
    split_mask<<<(BB * TT * HH / 4 + 255) / 256, 256>>>(tgt, tmask, p_tgt2, nullptr, BB * TT, HH);
    split_mask<<<(HH * HH / 4 + 255) / 256, 256>>>(W, nullptr, p_W2, nullptr, HH, HH);
    vT_split<<<dim3(TT / 32, HH / 32, BB), dim3(32, 8)>>>(tgt, p_vT2);

    // 1) seq_t = relu((seq*sm) @ W^T)  -> split bf16
    gemm_mma<0><<<dim3(HH / 128, (BB * SS) / 128, 1), 256, SMEM_DYN>>>(
        p_seq2, p_W2, 0, 0, HH, nullptr, nullptr, p_seqt2, nullptr, 0);

    // 2) tgt_t = relu((tgt*tm) @ W^T)  -> split bf16
    gemm_mma<0><<<dim3(HH / 128, (BB * TT) / 128, 1), 256, SMEM_DYN>>>(
        p_tgt2, p_W2, 0, 0, HH, nullptr, nullptr, p_tgtt2, nullptr, 0);

    // 3) logits[b] = seq_t[b] @ tgt_t[b]^T  -> fp32
    gemm_mma<1><<<dim3(TT / 128, SS / 128, BB), 256, SMEM_DYN>>>(
        p_seqt2, p_tgtt2, (long)SS * 2 * HH, (long)TT * 2 * HH, HH,
        p_logits, nullptr, nullptr, nullptr, 0);

    // 4) softmax + split
    softmax_split<<<BB * SS, 128>>>(p_logits, p_probs2);

    // 5) attn_out = P @ V^T-split, fused cat/attn epilogue
    gemm_mma<2><<<dim3(HH / 128, SS / 128, BB), 256, SMEM_DYN>>>(
        p_probs2, p_vT2, (long)SS * 2 * TT, (long)HH * 2 * TT, TT,
        out, out_attn, nullptr, smask, write_attn);
}

// round 9
// speedup vs baseline: 1.0470x; 1.0470x over previous
#include <cuda_runtime.h>
#include <cuda_bf16.h>
#include <cstdint>

#define BB 8
#define SS 4096
#define TT 512
#define HH 768

// ---------------------------------------------------------------------------
// Scratch (device .bss). Split bf16 operands: [R, 2C], hi in [0,C), lo in [C,2C).
// ---------------------------------------------------------------------------
__device__ __align__(16) __nv_bfloat16 g_seq2 [(size_t)BB * SS * 2 * HH];
__device__ __align__(16) __nv_bfloat16 g_tgt2 [(size_t)BB * TT * 2 * HH];
__device__ __align__(16) __nv_bfloat16 g_W2   [(size_t)HH * 2 * HH];
__device__ __align__(16) __nv_bfloat16 g_seqt2[(size_t)BB * SS * 2 * HH];
__device__ __align__(16) __nv_bfloat16 g_tgtt2[(size_t)BB * TT * 2 * HH];
__device__ __align__(16) float         g_logits[(size_t)BB * SS * TT];
__device__ __align__(16) __nv_bfloat16 g_probs2[(size_t)BB * SS * 2 * TT];
__device__ __align__(16) __nv_bfloat16 g_vT2  [(size_t)BB * HH * 2 * TT];  // [B, H, 2T]

// ---------------------------------------------------------------------------
// Helpers (baseline PTX: cp.async / ldmatrix / mma.sync — sm_80+ ISA)
// ---------------------------------------------------------------------------
__device__ __forceinline__ uint32_t smem_u32(const void* p) {
    uint32_t a;
    asm("{ .reg .u64 t; cvta.to.shared.u64 t, %1; cvt.u32.u64 %0, t; }" : "=r"(a) : "l"(p));
    return a;
}
__device__ __forceinline__ void cp16(uint32_t saddr, const void* g) {
    asm volatile("cp.async.cg.shared.global [%0], [%1], 16;" :: "r"(saddr), "l"(g) : "memory");
}
#define CP_COMMIT() asm volatile("cp.async.commit_group;" ::: "memory")
template <int N>
__device__ __forceinline__ void cp_wait() {
    asm volatile("cp.async.wait_group %0;" :: "n"(N) : "memory");
}
__device__ __forceinline__ void ldsm_x4(uint32_t* r, uint32_t addr) {
    asm volatile("ldmatrix.sync.aligned.m8n8.x4.shared.b16 {%0,%1,%2,%3}, [%4];"
        : "=r"(r[0]), "=r"(r[1]), "=r"(r[2]), "=r"(r[3]) : "r"(addr));
}
__device__ __forceinline__ void mma_bf16(float* c, const uint32_t* a, const uint32_t* b) {
    asm volatile(
        "mma.sync.aligned.m16n8k16.row.col.f32.bf16.bf16.f32 "
        "{%0,%1,%2,%3}, {%4,%5,%6,%7}, {%8,%9}, {%0,%1,%2,%3};"
        : "+f"(c[0]), "+f"(c[1]), "+f"(c[2]), "+f"(c[3])
        : "r"(a[0]), "r"(a[1]), "r"(a[2]), "r"(a[3]), "r"(b[0]), "r"(b[1]));
}
__device__ __forceinline__ void split1(float x, __nv_bfloat16& h, __nv_bfloat16& l) {
    h = __float2bfloat16(x);
    l = __float2bfloat16(x - __bfloat162float(h));
}

// ---------------------------------------------------------------------------
// HMMA GEMM: D = Ahi*Bhi + Alo*Bhi + Ahi*Blo (split-bf16 3-term).
// A: [rows, 2C] split bf16 K-major. B: [N, 2C] split bf16 K-major.
// CTA tile 128x128, BK=64, 3-buffer cp.async, single barrier per iteration
// (R7-proven loop: wait -> sync -> compute -> prefetch it+2).
// 256 threads = 8 warps (2m x 4n), warp tile 64x32. smem 96KB -> 2 CTAs/SM.
// EPI 0 additionally supports a MERGED second problem sharing the same B:
// blocks with blockIdx.y >= ySplit read A2/write obf2 (used to fuse the
// seq@W^T and tgt@W^T GEMMs into one launch, killing a wasted wave).
// EPI: 0 = relu + split-bf16; 1 = fp32; 2 = attn/cat.
// ---------------------------------------------------------------------------
template <int EPI>
__launch_bounds__(256)
__global__ void gemm_mma(const __nv_bfloat16* __restrict__ A,
                         const __nv_bfloat16* __restrict__ Bm,
                         long aBatch, long bBatch, int C,
                         float* __restrict__ out0, float* __restrict__ out1,
                         __nv_bfloat16* __restrict__ obf,
                         const int* __restrict__ smask, int writeAttn,
                         const __nv_bfloat16* __restrict__ A2,
                         __nv_bfloat16* __restrict__ obf2, int ySplit)
{
    extern __shared__ char smem[];
    const uint32_t sb = smem_u32(smem);

    const int tid = threadIdx.x;
    const int wid = tid >> 5;
    const int lane = tid & 31;

    const int z = blockIdx.z;
    const long Kr = 2L * C;

    // A-side / output selection (EPI 0 may host two merged problems)
    const __nv_bfloat16* Ab;
    __nv_bfloat16* obf_sel = obf;
    int m0;
    if (EPI == 0 && (int)blockIdx.y >= ySplit) {
        Ab = A2;
        m0 = ((int)blockIdx.y - ySplit) * 128;
        obf_sel = obf2;
    } else {
        Ab = A + (long)z * aBatch;
        m0 = blockIdx.y * 128;
    }
    const int n0 = blockIdx.x * 128;
    const __nv_bfloat16* Bb = Bm + (long)z * bBatch;

    const int kc = C >> 6;     // 64-col chunks per segment
    const int nk = 3 * kc;

    const int vr0 = tid >> 3;          // load row base (stride 32)
    const int vc16 = (tid & 7) * 16;   // byte offset in 128B row

#define LDG_STAGE(IT, S)                                                          \
    {                                                                             \
        int _it = (IT);                                                           \
        int _seg = (_it >= 2 * kc) ? 2 : ((_it >= kc) ? 1 : 0);                   \
        int _kl = _it - _seg * kc;                                                \
        long _aC = ((_seg == 1) ? C : 0) + (long)_kl * 64 + (vc16 >> 1);          \
        long _bC = ((_seg == 2) ? C : 0) + (long)_kl * 64 + (vc16 >> 1);          \
        uint32_t _sA = sb + (S) * 32768u;                                         \
        uint32_t _sB = _sA + 16384u;                                              \
        _Pragma("unroll")                                                         \
        for (int i = 0; i < 4; i++) {                                             \
            int r = vr0 + 32 * i;                                                 \
            uint32_t sw = (uint32_t)(r * 128 + (vc16 ^ ((r & 7) << 4)));          \
            cp16(_sA + sw, Ab + (long)(m0 + r) * Kr + _aC);                       \
            cp16(_sB + sw, Bb + (long)(n0 + r) * Kr + _bC);                       \
        }                                                                         \
    }

    // prologue: prefetch stages 0,1 into buffers 0,1 (buffer 2 free)
    LDG_STAGE(0, 0); CP_COMMIT();
    LDG_STAGE(1, 1); CP_COMMIT();

    const int wm = wid & 1;     // 0..1 -> 64 rows
    const int wn = wid >> 1;    // 0..3 -> 32 cols

    float acc[4][4][4] = {};

    const int arow = wm * 64 + (lane & 15);                     // + mt*16
    const int akb = (lane >> 4) * 16;
    const int brow = wn * 32 + (lane & 7) + ((lane >> 4) * 8);  // + ntp*16
    const int bkb = ((lane >> 3) & 1) * 16;

    for (int it = 0; it < nk; it++) {
        if (it + 1 < nk) cp_wait<1>(); else cp_wait<0>();
        __syncthreads();   // all warps done reading stage it-1

        const uint32_t stA = sb + (uint32_t)(it % 3) * 32768u;
        const uint32_t stB = stA + 16384u;

        #pragma unroll
        for (int ks = 0; ks < 4; ks++) {
            uint32_t afr[4][4], bfr[2][4];
            #pragma unroll
            for (int mt = 0; mt < 4; mt++) {
                const int row = arow + mt * 16;
                ldsm_x4(afr[mt], stA + row * 128 + ((ks * 32 + akb) ^ ((row & 7) << 4)));
            }
            #pragma unroll
            for (int ntp = 0; ntp < 2; ntp++) {
                const int row = brow + ntp * 16;
                ldsm_x4(bfr[ntp], stB + row * 128 + ((ks * 32 + bkb) ^ ((row & 7) << 4)));
            }
            #pragma unroll
            for (int mt = 0; mt < 4; mt++)
                #pragma unroll
                for (int nt = 0; nt < 4; nt++)
                    mma_bf16(acc[mt][nt], afr[mt], &bfr[nt >> 1][(nt & 1) * 2]);
        }

        // Prefetch stage it+2 into buffer (it+2)%3 == (it-1)%3 (race-free:
        // the barrier above proved every warp finished stage it-1).
        if (it + 2 < nk) { LDG_STAGE(it + 2, (it + 2) % 3); CP_COMMIT(); }
    }

    // ---- epilogue ----
    const int er = wm * 64 + (lane >> 2);        // + mt*16 (+8 for c2/c3)
    const int ec = wn * 32 + (lane & 3) * 2;     // + nt*8

    if (EPI == 0) {
        const int Nout = gridDim.x * 128;
        #pragma unroll
        for (int mt = 0; mt < 4; mt++)
            #pragma unroll
            for (int nt = 0; nt < 4; nt++)
                #pragma unroll
                for (int h = 0; h < 2; h++) {
                    const int row = m0 + er + mt * 16 + h * 8;
                    const int col = n0 + ec + nt * 8;
                    float x0 = fmaxf(acc[mt][nt][2 * h], 0.f);
                    float x1 = fmaxf(acc[mt][nt][2 * h + 1], 0.f);
                    __nv_bfloat16 h0, l0, h1, l1;
                    split1(x0, h0, l0); split1(x1, h1, l1);
                    __nv_bfloat16* oh = obf_sel + (long)row * 2 * Nout + col;
                    *reinterpret_cast<__nv_bfloat162*>(oh) = __nv_bfloat162(h0, h1);
                    *reinterpret_cast<__nv_bfloat162*>(oh + Nout) = __nv_bfloat162(l0, l1);
                }
    } else if (EPI == 1) {
        #pragma unroll
        for (int mt = 0; mt < 4; mt++)
            #pragma unroll
            for (int nt = 0; nt < 4; nt++)
                #pragma unroll
                for (int h = 0; h < 2; h++) {
                    const int row = m0 + er + mt * 16 + h * 8;
                    const int col = n0 + ec + nt * 8;
                    float2 v = make_float2(acc[mt][nt][2 * h], acc[mt][nt][2 * h + 1]);
                    *reinterpret_cast<float2*>(out0 + ((long)z * SS + row) * TT + col) = v;
                }
    } else {
        #pragma unroll
        for (int mt = 0; mt < 4; mt++)
            #pragma unroll
            for (int nt = 0; nt < 4; nt++)
                #pragma unroll
                for (int h = 0; h < 2; h++) {
                    const int row = m0 + er + mt * 16 + h * 8;
                    const int col = n0 + ec + nt * 8;
                    const long gs = (long)z * SS + row;
                    const float m = (float)smask[gs];
                    float2 v = make_float2(acc[mt][nt][2 * h], acc[mt][nt][2 * h + 1]);
                    if (writeAttn)
                        *reinterpret_cast<float2*>(out1 + gs * (long)HH + col) = v;
                    float2 vm = make_float2(v.x * m, v.y * m);
                    *reinterpret_cast<float2*>(out0 + gs * (long)(2 * HH) + HH + col) = vm;
                }
    }
#undef LDG_STAGE
}

// ---------------------------------------------------------------------------
// fp32 [R,C] (row-masked) -> split bf16 [R,2C]; optionally also writes the
// masked fp32 row into out_cat[row, 0:C] (cat first half, stride 2C).
// ---------------------------------------------------------------------------
__launch_bounds__(256)
__global__ void split_mask(const float* __restrict__ in, const int* __restrict__ mask,
                           __nv_bfloat16* __restrict__ out, float* __restrict__ cat,
                           int R, int C)
{
    const long idx = (long)blockIdx.x * blockDim.x + threadIdx.x;  // float4 units
    const long total = (long)R * C / 4;
    if (idx >= total) return;
    const long row = idx / (C / 4);
    const int c4 = (int)(idx % (C / 4));
    const float m = mask ? (float)mask[row] : 1.0f;
    float4 v = reinterpret_cast<const float4*>(in)[idx];
    v.x *= m; v.y *= m; v.z *= m; v.w *= m;
    __nv_bfloat16 h0, l0, h1, l1, h2, l2, h3, l3;
    split1(v.x, h0, l0); split1(v.y, h1, l1); split1(v.z, h2, l2); split1(v.w, h3, l3);
    __nv_bfloat16* oh = out + row * 2L * C + c4 * 4;
    __nv_bfloat16* ol = oh + C;
    reinterpret_cast<__nv_bfloat162*>(oh)[0] = __nv_bfloat162(h0, h1);
    reinterpret_cast<__nv_bfloat162*>(oh)[1] = __nv_bfloat162(h2, h3);
    reinterpret_cast<__nv_bfloat162*>(ol)[0] = __nv_bfloat162(l0, l1);
    reinterpret_cast<__nv_bfloat162*>(ol)[1] = __nv_bfloat162(l2, l3);
    if (cat)
        reinterpret_cast<float4*>(cat)[row * (long)(2 * C / 4) + c4] = v;
}

// ---------------------------------------------------------------------------
// V^T split: O[b,h,t] = split(V[b,t,h]);  O layout [B, H, 2T]
// ---------------------------------------------------------------------------
__global__ void vT_split(const float* __restrict__ V, __nv_bfloat16* __restrict__ O)
{
    __shared__ float tile[32][33];
    const int b = blockIdx.z;
    const int t0 = blockIdx.x * 32, h0 = blockIdx.y * 32;
    const int tx = threadIdx.x, ty = threadIdx.y;  // 32 x 8
    #pragma unroll
    for (int i = 0; i < 32; i += 8)
        tile[ty + i][tx] = V[((long)b * TT + t0 + ty + i) * HH + h0 + tx];
    __syncthreads();
    #pragma unroll
    for (int i = 0; i < 32; i += 8) {
        const int h = h0 + ty + i, t = t0 + tx;
        __nv_bfloat16 hh, ll;
        split1(tile[tx][ty + i], hh, ll);
        const long base = ((long)b * HH + h) * (2L * TT) + t;
        O[base] = hh; O[base + TT] = ll;
    }
}

// ---------------------------------------------------------------------------
// Row softmax over T=512 + split-bf16 probs write.
// ---------------------------------------------------------------------------
__launch_bounds__(128)
__global__ void softmax_split(const float* __restrict__ logits, __nv_bfloat16* __restrict__ P2)
{
    const long row = blockIdx.x;
    const float* p = logits + row * TT;
    const int tid = threadIdx.x;
    const int warp = tid >> 5, lane = tid & 31;

    float v[4];
    #pragma unroll
    for (int i = 0; i < 4; i++) v[i] = p[tid + 128 * i];

    float mx = fmaxf(fmaxf(v[0], v[1]), fmaxf(v[2], v[3]));
    #pragma unroll
    for (int o = 16; o > 0; o >>= 1) mx = fmaxf(mx, __shfl_xor_sync(0xffffffffu, mx, o));
    __shared__ float smx[4];
    if (lane == 0) smx[warp] = mx;
    __syncthreads();
    mx = fmaxf(fmaxf(smx[0], smx[1]), fmaxf(smx[2], smx[3]));

    float sum = 0.f;
    #pragma unroll
    for (int i = 0; i < 4; i++) { v[i] = __expf(v[i] - mx); sum += v[i]; }
    #pragma unroll
    for (int o = 16; o > 0; o >>= 1) sum += __shfl_xor_sync(0xffffffffu, sum, o);
    __shared__ float ssum[4];
    if (lane == 0) ssum[warp] = sum;
    __syncthreads();
    const float inv = 1.0f / (ssum[0] + ssum[1] + ssum[2] + ssum[3]);

    __nv_bfloat16* out = P2 + row * 2L * TT;
    #pragma unroll
    for (int i = 0; i < 4; i++) {
        const int idx = tid + 128 * i;
        __nv_bfloat16 h, l;
        split1(v[i] * inv, h, l);
        out[idx] = h; out[TT + idx] = l;
    }
}

// ---------------------------------------------------------------------------

extern "C" void kernel_launch(void* const* d_in, const int* in_sizes, int n_in,
                              void* d_out, int out_size)
{
    const float* seq   = (const float*)d_in[0];
    const int*   smask = (const int*)d_in[1];
    const float* tgt   = (const float*)d_in[2];
    const int*   tmask = (const int*)d_in[3];
    const float* W     = (const float*)d_in[4];
    float* out = (float*)d_out;

    __nv_bfloat16 *p_seq2, *p_tgt2, *p_W2, *p_seqt2, *p_tgtt2, *p_probs2, *p_vT2;
    float* p_logits;
    cudaGetSymbolAddress((void**)&p_seq2, g_seq2);
    cudaGetSymbolAddress((void**)&p_tgt2, g_tgt2);
    cudaGetSymbolAddress((void**)&p_W2, g_W2);
    cudaGetSymbolAddress((void**)&p_seqt2, g_seqt2);
    cudaGetSymbolAddress((void**)&p_tgtt2, g_tgtt2);
    cudaGetSymbolAddress((void**)&p_logits, g_logits);
    cudaGetSymbolAddress((void**)&p_probs2, g_probs2);
    cudaGetSymbolAddress((void**)&p_vT2, g_vT2);

    const int write_attn = (out_size >= BB * SS * 3 * HH) ? 1 : 0;
    float* out_attn = out + (size_t)BB * SS * 2 * HH;

    const int SMEM_DYN = 3 * 32768;  // 98304 -> 2 CTAs/SM
    cudaFuncSetAttribute(gemm_mma<0>, cudaFuncAttributeMaxDynamicSharedMemorySize, SMEM_DYN);
    cudaFuncSetAttribute(gemm_mma<1>, cudaFuncAttributeMaxDynamicSharedMemorySize, SMEM_DYN);
    cudaFuncSetAttribute(gemm_mma<2>, cudaFuncAttributeMaxDynamicSharedMemorySize, SMEM_DYN);

    // 0) operand conversions (seq variant also writes cat first half)
    split_mask<<<(BB * SS * HH / 4 + 255) / 256, 256>>>(seq, smask, p_seq2, out, BB * SS, HH);
    split_mask<<<(BB * TT * HH / 4 + 255) / 256, 256>>>(tgt, tmask, p_tgt2, nullptr, BB * TT, HH);
    split_mask<<<(HH * HH / 4 + 255) / 256, 256>>>(W, nullptr, p_W2, nullptr, HH, HH);
    vT_split<<<dim3(TT / 32, HH / 32, BB), dim3(32, 8)>>>(tgt, p_vT2);

    // 1+2 merged) seq_t AND tgt_t = relu(X @ W^T) -> split bf16, one launch.
    //   y-blocks [0, 256): seq rows; [256, 288): tgt rows.
    const int Y_SEQ = (BB * SS) / 128;   // 256
    const int Y_TGT = (BB * TT) / 128;   // 32
    gemm_mma<0><<<dim3(HH / 128, Y_SEQ + Y_TGT, 1), 256, SMEM_DYN>>>(
        p_seq2, p_W2, 0, 0, HH, nullptr, nullptr, p_seqt2, nullptr, 0,
        p_tgt2, p_tgtt2, Y_SEQ);

    // 3) logits[b] = seq_t[b] @ tgt_t[b]^T  -> fp32
    gemm_mma<1><<<dim3(TT / 128, SS / 128, BB), 256, SMEM_DYN>>>(
        p_seqt2, p_tgtt2, (long)SS * 2 * HH, (long)TT * 2 * HH, HH,
        p_logits, nullptr, nullptr, nullptr, 0, nullptr, nullptr, 1 << 30);

    // 4) softmax + split
    softmax_split<<<BB * SS, 128>>>(p_logits, p_probs2);

    // 5) attn_out = P @ V^T-split, fused cat/attn epilogue
    gemm_mma<2><<<dim3(HH / 128, SS / 128, BB), 256, SMEM_DYN>>>(
        p_probs2, p_vT2, (long)SS * 2 * TT, (long)HH * 2 * TT, TT,
        out, out_attn, nullptr, smask, write_attn, nullptr, nullptr, 1 << 30);
}

// round 10
// speedup vs baseline: 1.4310x; 1.3668x over previous
#include <cuda_runtime.h>
#include <cuda_bf16.h>
#include <cstdint>

#define BB 8
#define SS 4096
#define TT 512
#define HH 768

// ---------------------------------------------------------------------------
// Scratch (device .bss). Split bf16 operands: [R, 2C], hi in [0,C), lo in [C,2C).
// seq-side buffers are COMPACTED per batch (unmasked rows first, cnt[b] valid).
// ---------------------------------------------------------------------------
__device__ __align__(16) __nv_bfloat16 g_seq2 [(size_t)BB * SS * 2 * HH];  // compacted
__device__ __align__(16) __nv_bfloat16 g_tgt2 [(size_t)BB * TT * 2 * HH];  // full, masked
__device__ __align__(16) __nv_bfloat16 g_W2   [(size_t)HH * 2 * HH];
__device__ __align__(16) __nv_bfloat16 g_seqt2[(size_t)BB * SS * 2 * HH];  // compacted
__device__ __align__(16) __nv_bfloat16 g_tgtt2[(size_t)BB * TT * 2 * HH];  // full
__device__ __align__(16) float         g_logits[(size_t)BB * SS * TT];     // compacted rows
__device__ __align__(16) __nv_bfloat16 g_probs2[(size_t)BB * SS * 2 * TT]; // compacted rows
__device__ __align__(16) __nv_bfloat16 g_vT2  [(size_t)BB * HH * 2 * TT];  // [B, H, 2T] full
__device__ int   g_idx[BB * SS];   // compact j -> original row s (per batch)
__device__ int   g_cnt[BB];        // unmasked rows per batch
__device__ float g_cm [BB * HH];   // (1/T) * sum_t V[b,t,h]

// ---------------------------------------------------------------------------
// Helpers (baseline PTX: cp.async / ldmatrix / mma.sync — sm_80+ ISA)
// ---------------------------------------------------------------------------
__device__ __forceinline__ uint32_t smem_u32(const void* p) {
    uint32_t a;
    asm("{ .reg .u64 t; cvta.to.shared.u64 t, %1; cvt.u32.u64 %0, t; }" : "=r"(a) : "l"(p));
    return a;
}
__device__ __forceinline__ void cp16(uint32_t saddr, const void* g) {
    asm volatile("cp.async.cg.shared.global [%0], [%1], 16;" :: "r"(saddr), "l"(g) : "memory");
}
#define CP_COMMIT() asm volatile("cp.async.commit_group;" ::: "memory")
template <int N>
__device__ __forceinline__ void cp_wait() {
    asm volatile("cp.async.wait_group %0;" :: "n"(N) : "memory");
}
__device__ __forceinline__ void ldsm_x4(uint32_t* r, uint32_t addr) {
    asm volatile("ldmatrix.sync.aligned.m8n8.x4.shared.b16 {%0,%1,%2,%3}, [%4];"
        : "=r"(r[0]), "=r"(r[1]), "=r"(r[2]), "=r"(r[3]) : "r"(addr));
}
__device__ __forceinline__ void mma_bf16(float* c, const uint32_t* a, const uint32_t* b) {
    asm volatile(
        "mma.sync.aligned.m16n8k16.row.col.f32.bf16.bf16.f32 "
        "{%0,%1,%2,%3}, {%4,%5,%6,%7}, {%8,%9}, {%0,%1,%2,%3};"
        : "+f"(c[0]), "+f"(c[1]), "+f"(c[2]), "+f"(c[3])
        : "r"(a[0]), "r"(a[1]), "r"(a[2]), "r"(a[3]), "r"(b[0]), "r"(b[1]));
}
__device__ __forceinline__ void split1(float x, __nv_bfloat16& h, __nv_bfloat16& l) {
    h = __float2bfloat16(x);
    l = __float2bfloat16(x - __bfloat162float(h));
}

// ---------------------------------------------------------------------------
// Per-batch ordered compaction of unmasked rows. 1024 threads x 4 elems = 4096.
// ---------------------------------------------------------------------------
__global__ void compact_index(const int* __restrict__ mask, int* __restrict__ idx,
                              int* __restrict__ cnt)
{
    const int b = blockIdx.x;
    const int tid = threadIdx.x;
    const int lane = tid & 31, w = tid >> 5;
    const int* m = mask + (long)b * SS;

    int v[4], c = 0;
    #pragma unroll
    for (int i = 0; i < 4; i++) { v[i] = m[tid * 4 + i]; c += v[i]; }

    int sc = c;   // inclusive warp scan
    #pragma unroll
    for (int o = 1; o < 32; o <<= 1) {
        int t = __shfl_up_sync(0xffffffffu, sc, o);
        if (lane >= o) sc += t;
    }
    __shared__ int ws[32];
    if (lane == 31) ws[w] = sc;
    __syncthreads();
    if (w == 0) {
        int t = ws[lane];
        #pragma unroll
        for (int o = 1; o < 32; o <<= 1) {
            int u = __shfl_up_sync(0xffffffffu, t, o);
            if (lane >= o) t += u;
        }
        ws[lane] = t;
    }
    __syncthreads();
    int base = sc - c + (w ? ws[w - 1] : 0);
    #pragma unroll
    for (int i = 0; i < 4; i++)
        if (v[i]) idx[(long)b * SS + base++] = tid * 4 + i;
    if (tid == 0) cnt[b] = ws[31];
}

// ---------------------------------------------------------------------------
// cat first half: out[row, 0:H] = seq * mask(row)   (masked rows -> 0)
// ---------------------------------------------------------------------------
__launch_bounds__(256)
__global__ void cat_first(const float* __restrict__ seq, const int* __restrict__ mask,
                          float* __restrict__ cat)
{
    const long t = (long)blockIdx.x * 256 + threadIdx.x;
    const long total = (long)BB * SS * (HH / 4);
    if (t >= total) return;
    const long row = t / (HH / 4);
    const int c4 = (int)(t % (HH / 4));
    const float m = (float)mask[row];
    float4 v = reinterpret_cast<const float4*>(seq)[row * (HH / 4) + c4];
    v.x *= m; v.y *= m; v.z *= m; v.w *= m;
    reinterpret_cast<float4*>(cat)[row * (2 * HH / 4) + c4] = v;
}

// ---------------------------------------------------------------------------
// Gather unmasked seq rows into compacted split-bf16 buffer [B][SS][2H].
// ---------------------------------------------------------------------------
__launch_bounds__(256)
__global__ void seq_compact_split(const float* __restrict__ seq, const int* __restrict__ idx,
                                  const int* __restrict__ cnt, __nv_bfloat16* __restrict__ out)
{
    const long t = (long)blockIdx.x * 256 + threadIdx.x;
    const long total = (long)BB * SS * (HH / 4);
    if (t >= total) return;
    const long crow = t / (HH / 4);
    const int c4 = (int)(t % (HH / 4));
    const int b = (int)(crow >> 12);      // / SS
    const int j = (int)(crow & (SS - 1));
    if (j >= cnt[b]) return;
    const int orig = idx[(long)b * SS + j];
    float4 v = reinterpret_cast<const float4*>(seq)[(((long)b * SS + orig) * HH) / 4 + c4];
    __nv_bfloat16 h0, l0, h1, l1, h2, l2, h3, l3;
    split1(v.x, h0, l0); split1(v.y, h1, l1); split1(v.z, h2, l2); split1(v.w, h3, l3);
    __nv_bfloat16* oh = out + crow * 2L * HH + c4 * 4;
    __nv_bfloat16* ol = oh + HH;
    reinterpret_cast<__nv_bfloat162*>(oh)[0] = __nv_bfloat162(h0, h1);
    reinterpret_cast<__nv_bfloat162*>(oh)[1] = __nv_bfloat162(h2, h3);
    reinterpret_cast<__nv_bfloat162*>(ol)[0] = __nv_bfloat162(l0, l1);
    reinterpret_cast<__nv_bfloat162*>(ol)[1] = __nv_bfloat162(l2, l3);
}

// Zero the pad rows [cnt[b], ceil128(cnt[b])) of the compacted seq2 buffer.
__global__ void zero_pad(const int* __restrict__ cnt, __nv_bfloat16* __restrict__ seq2)
{
    const int b = blockIdx.x;
    const int c = cnt[b];
    const int e = min((c + 127) & ~127, SS);
    const long nU4 = (long)(e - c) * (2 * HH / 8);   // uint4 per pad region
    uint4* base = reinterpret_cast<uint4*>(seq2 + ((long)b * SS + c) * 2 * HH);
    const uint4 z = make_uint4(0, 0, 0, 0);
    for (long i = threadIdx.x; i < nU4; i += 256) base[i] = z;
}

// ---------------------------------------------------------------------------
// fp32 [R,C] (row-masked) -> split bf16 [R,2C]  (used for tgt and W)
// ---------------------------------------------------------------------------
__launch_bounds__(256)
__global__ void split_mask(const float* __restrict__ in, const int* __restrict__ mask,
                           __nv_bfloat16* __restrict__ out, int R, int C)
{
    const long idx = (long)blockIdx.x * blockDim.x + threadIdx.x;
    const long total = (long)R * C / 4;
    if (idx >= total) return;
    const long row = idx / (C / 4);
    const int c4 = (int)(idx % (C / 4));
    const float m = mask ? (float)mask[row] : 1.0f;
    float4 v = reinterpret_cast<const float4*>(in)[idx];
    v.x *= m; v.y *= m; v.z *= m; v.w *= m;
    __nv_bfloat16 h0, l0, h1, l1, h2, l2, h3, l3;
    split1(v.x, h0, l0); split1(v.y, h1, l1); split1(v.z, h2, l2); split1(v.w, h3, l3);
    __nv_bfloat16* oh = out + row * 2L * C + c4 * 4;
    __nv_bfloat16* ol = oh + C;
    reinterpret_cast<__nv_bfloat162*>(oh)[0] = __nv_bfloat162(h0, h1);
    reinterpret_cast<__nv_bfloat162*>(oh)[1] = __nv_bfloat162(h2, h3);
    reinterpret_cast<__nv_bfloat162*>(ol)[0] = __nv_bfloat162(l0, l1);
    reinterpret_cast<__nv_bfloat162*>(ol)[1] = __nv_bfloat162(l2, l3);
}

// ---------------------------------------------------------------------------
// V^T split: O[b,h,t] = split(V[b,t,h]);  O layout [B, H, 2T]
// ---------------------------------------------------------------------------
__global__ void vT_split(const float* __restrict__ V, __nv_bfloat16* __restrict__ O)
{
    __shared__ float tile[32][33];
    const int b = blockIdx.z;
    const int t0 = blockIdx.x * 32, h0 = blockIdx.y * 32;
    const int tx = threadIdx.x, ty = threadIdx.y;  // 32 x 8
    #pragma unroll
    for (int i = 0; i < 32; i += 8)
        tile[ty + i][tx] = V[((long)b * TT + t0 + ty + i) * HH + h0 + tx];
    __syncthreads();
    #pragma unroll
    for (int i = 0; i < 32; i += 8) {
        const int h = h0 + ty + i, t = t0 + tx;
        __nv_bfloat16 hh, ll;
        split1(tile[tx][ty + i], hh, ll);
        const long base = ((long)b * HH + h) * (2L * TT) + t;
        O[base] = hh; O[base + TT] = ll;
    }
}

// ---------------------------------------------------------------------------
// colmean[b,h] = (1/T) * sum_t V[b,t,h]   (exact closed form for masked rows)
// ---------------------------------------------------------------------------
__launch_bounds__(256)
__global__ void colmean_k(const float* __restrict__ V, float* __restrict__ cm)
{
    const int t = blockIdx.x * 256 + threadIdx.x;
    if (t >= BB * HH) return;
    const int b = t / HH, h = t % HH;
    const float* p = V + (long)b * TT * HH + h;
    float s = 0.f;
    #pragma unroll 4
    for (int i = 0; i < TT; i++) s += p[(long)i * HH];
    cm[t] = s * (1.0f / TT);
}

// ---------------------------------------------------------------------------
// Masked rows: attn_out = colmean, cat second half = 0.
// ---------------------------------------------------------------------------
__launch_bounds__(256)
__global__ void fill_masked(const int* __restrict__ mask, const float* __restrict__ cm,
                            float* __restrict__ cat, float* __restrict__ attn, int writeAttn)
{
    const long t = (long)blockIdx.x * 256 + threadIdx.x;
    const long total = (long)BB * SS * (HH / 4);
    if (t >= total) return;
    const long row = t / (HH / 4);
    const int c4 = (int)(t % (HH / 4));
    if (mask[row]) return;
    const int b = (int)(row >> 12);
    float4 v = reinterpret_cast<const float4*>(cm)[(long)b * (HH / 4) + c4];
    if (writeAttn)
        reinterpret_cast<float4*>(attn)[row * (HH / 4) + c4] = v;
    reinterpret_cast<float4*>(cat)[row * (2 * HH / 4) + (HH / 4) + c4] = make_float4(0, 0, 0, 0);
}

// ---------------------------------------------------------------------------
// HMMA GEMM: D = Ahi*Bhi + Alo*Bhi + Ahi*Blo (split-bf16 3-term).
// CTA 128x128, BK=64, 3-buffer cp.async, R7-proven single-barrier loop.
// Compaction-aware: EPI0 seq part and EPI1/EPI2 early-exit past cnt[b];
// EPI2 scatters rows through idx with a bounds guard.
// ---------------------------------------------------------------------------
template <int EPI>
__launch_bounds__(256)
__global__ void gemm_mma(const __nv_bfloat16* __restrict__ A,
                         const __nv_bfloat16* __restrict__ Bm,
                         long aBatch, long bBatch, int C,
                         float* __restrict__ out0, float* __restrict__ out1,
                         __nv_bfloat16* __restrict__ obf,
                         int writeAttn,
                         const __nv_bfloat16* __restrict__ A2,
                         __nv_bfloat16* __restrict__ obf2, int ySplit,
                         const int* __restrict__ cntp, const int* __restrict__ idxp)
{
    extern __shared__ char smem[];
    const uint32_t sb = smem_u32(smem);

    const int tid = threadIdx.x;
    const int wid = tid >> 5;
    const int lane = tid & 31;

    const int z = blockIdx.z;
    const long Kr = 2L * C;

    const __nv_bfloat16* Ab;
    __nv_bfloat16* obf_sel = obf;
    long orow = 0;
    int m0, cb = SS;
    if (EPI == 0) {
        if ((int)blockIdx.y < ySplit) {
            const int b = blockIdx.y >> 5;              // 32 y-blocks per batch
            m0 = (blockIdx.y & 31) * 128;
            if (m0 >= cntp[b]) return;                  // compacted: skip dead blocks
            Ab = A + (long)b * aBatch;
            orow = (long)b * SS;
        } else {
            m0 = ((int)blockIdx.y - ySplit) * 128;      // tgt part: full rows
            Ab = A2; obf_sel = obf2;
        }
    } else {
        m0 = blockIdx.y * 128;
        cb = cntp[z];
        if (m0 >= cb) return;
        Ab = A + (long)z * aBatch;
    }
    const int n0 = blockIdx.x * 128;
    const __nv_bfloat16* Bb = Bm + (long)z * bBatch;

    const int kc = C >> 6;
    const int nk = 3 * kc;

    const int vr0 = tid >> 3;
    const int vc16 = (tid & 7) * 16;

#define LDG_STAGE(IT, S)                                                          \
    {                                                                             \
        int _it = (IT);                                                           \
        int _seg = (_it >= 2 * kc) ? 2 : ((_it >= kc) ? 1 : 0);                   \
        int _kl = _it - _seg * kc;                                                \
        long _aC = ((_seg == 1) ? C : 0) + (long)_kl * 64 + (vc16 >> 1);          \
        long _bC = ((_seg == 2) ? C : 0) + (long)_kl * 64 + (vc16 >> 1);          \
        uint32_t _sA = sb + (S) * 32768u;                                         \
        uint32_t _sB = _sA + 16384u;                                              \
        _Pragma("unroll")                                                         \
        for (int i = 0; i < 4; i++) {                                             \
            int r = vr0 + 32 * i;                                                 \
            uint32_t sw = (uint32_t)(r * 128 + (vc16 ^ ((r & 7) << 4)));          \
            cp16(_sA + sw, Ab + (long)(m0 + r) * Kr + _aC);                       \
            cp16(_sB + sw, Bb + (long)(n0 + r) * Kr + _bC);                       \
        }                                                                         \
    }

    LDG_STAGE(0, 0); CP_COMMIT();
    LDG_STAGE(1, 1); CP_COMMIT();

    const int wm = wid & 1;
    const int wn = wid >> 1;

    float acc[4][4][4] = {};

    const int arow = wm * 64 + (lane & 15);
    const int akb = (lane >> 4) * 16;
    const int brow = wn * 32 + (lane & 7) + ((lane >> 4) * 8);
    const int bkb = ((lane >> 3) & 1) * 16;

    for (int it = 0; it < nk; it++) {
        if (it + 1 < nk) cp_wait<1>(); else cp_wait<0>();
        __syncthreads();

        const uint32_t stA = sb + (uint32_t)(it % 3) * 32768u;
        const uint32_t stB = stA + 16384u;

        #pragma unroll
        for (int ks = 0; ks < 4; ks++) {
            uint32_t afr[4][4], bfr[2][4];
            #pragma unroll
            for (int mt = 0; mt < 4; mt++) {
                const int row = arow + mt * 16;
                ldsm_x4(afr[mt], stA + row * 128 + ((ks * 32 + akb) ^ ((row & 7) << 4)));
            }
            #pragma unroll
            for (int ntp = 0; ntp < 2; ntp++) {
                const int row = brow + ntp * 16;
                ldsm_x4(bfr[ntp], stB + row * 128 + ((ks * 32 + bkb) ^ ((row & 7) << 4)));
            }
            #pragma unroll
            for (int mt = 0; mt < 4; mt++)
                #pragma unroll
                for (int nt = 0; nt < 4; nt++)
                    mma_bf16(acc[mt][nt], afr[mt], &bfr[nt >> 1][(nt & 1) * 2]);
        }

        if (it + 2 < nk) { LDG_STAGE(it + 2, (it + 2) % 3); CP_COMMIT(); }
    }

    // ---- epilogue ----
    const int er = wm * 64 + (lane >> 2);
    const int ec = wn * 32 + (lane & 3) * 2;

    if (EPI == 0) {
        const int Nout = gridDim.x * 128;
        #pragma unroll
        for (int mt = 0; mt < 4; mt++)
            #pragma unroll
            for (int nt = 0; nt < 4; nt++)
                #pragma unroll
                for (int h = 0; h < 2; h++) {
                    const long row = orow + m0 + er + mt * 16 + h * 8;
                    const int col = n0 + ec + nt * 8;
                    float x0 = fmaxf(acc[mt][nt][2 * h], 0.f);
                    float x1 = fmaxf(acc[mt][nt][2 * h + 1], 0.f);
                    __nv_bfloat16 h0, l0, h1, l1;
                    split1(x0, h0, l0); split1(x1, h1, l1);
                    __nv_bfloat16* oh = obf_sel + row * 2 * Nout + col;
                    *reinterpret_cast<__nv_bfloat162*>(oh) = __nv_bfloat162(h0, h1);
                    *reinterpret_cast<__nv_bfloat162*>(oh + Nout) = __nv_bfloat162(l0, l1);
                }
    } else if (EPI == 1) {
        #pragma unroll
        for (int mt = 0; mt < 4; mt++)
            #pragma unroll
            for (int nt = 0; nt < 4; nt++)
                #pragma unroll
                for (int h = 0; h < 2; h++) {
                    const int row = m0 + er + mt * 16 + h * 8;
                    const int col = n0 + ec + nt * 8;
                    float2 v = make_float2(acc[mt][nt][2 * h], acc[mt][nt][2 * h + 1]);
                    *reinterpret_cast<float2*>(out0 + ((long)z * SS + row) * TT + col) = v;
                }
    } else {
        const long zb = (long)z * SS;
        #pragma unroll
        for (int mt = 0; mt < 4; mt++)
            #pragma unroll
            for (int h = 0; h < 2; h++) {
                const int local = m0 + er + mt * 16 + h * 8;
                if (local < cb) {                       // guard pad rows
                    const long gs = zb + idxp[zb + local];  // scatter to original row
                    #pragma unroll
                    for (int nt = 0; nt < 4; nt++) {
                        const int col = n0 + ec + nt * 8;
                        float2 v = make_float2(acc[mt][nt][2 * h], acc[mt][nt][2 * h + 1]);
                        if (writeAttn)
                            *reinterpret_cast<float2*>(out1 + gs * (long)HH + col) = v;
                        *reinterpret_cast<float2*>(out0 + gs * (long)(2 * HH) + HH + col) = v;
                    }
                }
            }
    }
#undef LDG_STAGE
}

// ---------------------------------------------------------------------------
// Row softmax over T=512 + split-bf16 probs write (compacted rows only).
// ---------------------------------------------------------------------------
__launch_bounds__(128)
__global__ void softmax_split(const float* __restrict__ logits, __nv_bfloat16* __restrict__ P2,
                              const int* __restrict__ cnt)
{
    const long row = blockIdx.x;
    const int b = (int)(row >> 12);
    if ((int)(row & (SS - 1)) >= cnt[b]) return;
    const float* p = logits + row * TT;
    const int tid = threadIdx.x;
    const int warp = tid >> 5, lane = tid & 31;

    float v[4];
    #pragma unroll
    for (int i = 0; i < 4; i++) v[i] = p[tid + 128 * i];

    float mx = fmaxf(fmaxf(v[0], v[1]), fmaxf(v[2], v[3]));
    #pragma unroll
    for (int o = 16; o > 0; o >>= 1) mx = fmaxf(mx, __shfl_xor_sync(0xffffffffu, mx, o));
    __shared__ float smx[4];
    if (lane == 0) smx[warp] = mx;
    __syncthreads();
    mx = fmaxf(fmaxf(smx[0], smx[1]), fmaxf(smx[2], smx[3]));

    float sum = 0.f;
    #pragma unroll
    for (int i = 0; i < 4; i++) { v[i] = __expf(v[i] - mx); sum += v[i]; }
    #pragma unroll
    for (int o = 16; o > 0; o >>= 1) sum += __shfl_xor_sync(0xffffffffu, sum, o);
    __shared__ float ssum[4];
    if (lane == 0) ssum[warp] = sum;
    __syncthreads();
    const float inv = 1.0f / (ssum[0] + ssum[1] + ssum[2] + ssum[3]);

    __nv_bfloat16* out = P2 + row * 2L * TT;
    #pragma unroll
    for (int i = 0; i < 4; i++) {
        const int idx = tid + 128 * i;
        __nv_bfloat16 h, l;
        split1(v[i] * inv, h, l);
        out[idx] = h; out[TT + idx] = l;
    }
}

// ---------------------------------------------------------------------------

extern "C" void kernel_launch(void* const* d_in, const int* in_sizes, int n_in,
                              void* d_out, int out_size)
{
    const float* seq   = (const float*)d_in[0];
    const int*   smask = (const int*)d_in[1];
    const float* tgt   = (const float*)d_in[2];
    const int*   tmask = (const int*)d_in[3];
    const float* W     = (const float*)d_in[4];
    float* out = (float*)d_out;

    __nv_bfloat16 *p_seq2, *p_tgt2, *p_W2, *p_seqt2, *p_tgtt2, *p_probs2, *p_vT2;
    float *p_logits, *p_cm;
    int *p_idx, *p_cnt;
    cudaGetSymbolAddress((void**)&p_seq2, g_seq2);
    cudaGetSymbolAddress((void**)&p_tgt2, g_tgt2);
    cudaGetSymbolAddress((void**)&p_W2, g_W2);
    cudaGetSymbolAddress((void**)&p_seqt2, g_seqt2);
    cudaGetSymbolAddress((void**)&p_tgtt2, g_tgtt2);
    cudaGetSymbolAddress((void**)&p_logits, g_logits);
    cudaGetSymbolAddress((void**)&p_probs2, g_probs2);
    cudaGetSymbolAddress((void**)&p_vT2, g_vT2);
    cudaGetSymbolAddress((void**)&p_idx, g_idx);
    cudaGetSymbolAddress((void**)&p_cnt, g_cnt);
    cudaGetSymbolAddress((void**)&p_cm, g_cm);

    const int write_attn = (out_size >= BB * SS * 3 * HH) ? 1 : 0;
    float* out_attn = out + (size_t)BB * SS * 2 * HH;

    const int SMEM_DYN = 3 * 32768;  // 96KB -> 2 CTAs/SM
    cudaFuncSetAttribute(gemm_mma<0>, cudaFuncAttributeMaxDynamicSharedMemorySize, SMEM_DYN);
    cudaFuncSetAttribute(gemm_mma<1>, cudaFuncAttributeMaxDynamicSharedMemorySize, SMEM_DYN);
    cudaFuncSetAttribute(gemm_mma<2>, cudaFuncAttributeMaxDynamicSharedMemorySize, SMEM_DYN);

    const int NCHUNK = (BB * SS * (HH / 4) + 255) / 256;  // 24576 blocks

    // 0) compaction + operand conversions
    compact_index<<<BB, 1024>>>(smask, p_idx, p_cnt);
    cat_first<<<NCHUNK, 256>>>(seq, smask, out);
    seq_compact_split<<<NCHUNK, 256>>>(seq, p_idx, p_cnt, p_seq2);
    zero_pad<<<BB, 256>>>(p_cnt, p_seq2);
    split_mask<<<(BB * TT * HH / 4 + 255) / 256, 256>>>(tgt, tmask, p_tgt2, BB * TT, HH);
    split_mask<<<(HH * HH / 4 + 255) / 256, 256>>>(W, nullptr, p_W2, HH, HH);
    vT_split<<<dim3(TT / 32, HH / 32, BB), dim3(32, 8)>>>(tgt, p_vT2);
    colmean_k<<<(BB * HH + 255) / 256, 256>>>(tgt, p_cm);

    // 1+2 merged) seq_t (compacted) AND tgt_t = relu(X @ W^T), one launch
    const int Y_SEQ = (BB * SS) / 128;   // 256 (32 per batch)
    const int Y_TGT = (BB * TT) / 128;   // 32
    gemm_mma<0><<<dim3(HH / 128, Y_SEQ + Y_TGT, 1), 256, SMEM_DYN>>>(
        p_seq2, p_W2, (long)SS * 2 * HH, 0, HH, nullptr, nullptr, p_seqt2, 0,
        p_tgt2, p_tgtt2, Y_SEQ, p_cnt, nullptr);

    // 3) logits[b] = seq_t[b] @ tgt_t[b]^T  (compacted rows)
    gemm_mma<1><<<dim3(TT / 128, SS / 128, BB), 256, SMEM_DYN>>>(
        p_seqt2, p_tgtt2, (long)SS * 2 * HH, (long)TT * 2 * HH, HH,
        p_logits, nullptr, nullptr, 0, nullptr, nullptr, 1 << 30, p_cnt, nullptr);

    // 4) softmax + split (compacted rows)
    softmax_split<<<BB * SS, 128>>>(p_logits, p_probs2, p_cnt);

    // 5) attn_out = P @ V, scatter epilogue to original rows
    gemm_mma<2><<<dim3(HH / 128, SS / 128, BB), 256, SMEM_DYN>>>(
        p_probs2, p_vT2, (long)SS * 2 * TT, (long)HH * 2 * TT, TT,
        out, out_attn, nullptr, write_attn, nullptr, nullptr, 1 << 30, p_cnt, p_idx);

    // 6) masked rows: attn = colmean(V), cat second half = 0
    fill_masked<<<NCHUNK, 256>>>(smask, p_cm, out, out_attn, write_attn);
}

// round 11
// speedup vs baseline: 1.5443x; 1.0792x over previous
#include <cuda_runtime.h>
#include <cuda_bf16.h>
#include <cstdint>

#define BB 8
#define SS 4096
#define TT 512
#define HH 768

// ---------------------------------------------------------------------------
// Scratch. Split bf16: [R, 2C], hi in [0,C), lo in [C,2C).
// seq-side AND tgt-side buffers are COMPACTED per batch (unmasked rows first).
// ---------------------------------------------------------------------------
__device__ __align__(16) __nv_bfloat16 g_seq2 [(size_t)BB * SS * 2 * HH];  // compacted
__device__ __align__(16) __nv_bfloat16 g_tgt2 [(size_t)BB * TT * 2 * HH];  // compacted
__device__ __align__(16) __nv_bfloat16 g_W2   [(size_t)HH * 2 * HH];
__device__ __align__(16) __nv_bfloat16 g_seqt2[(size_t)BB * SS * 2 * HH];  // compacted
__device__ __align__(16) __nv_bfloat16 g_tgtt2[(size_t)BB * TT * 2 * HH];  // compacted
__device__ __align__(16) float         g_logits[(size_t)BB * SS * TT];     // compact rows+cols
__device__ __align__(16) __nv_bfloat16 g_probs2[(size_t)BB * SS * 2 * TT]; // compact rows, full T
__device__ __align__(16) __nv_bfloat16 g_vT2  [(size_t)BB * HH * 2 * TT];  // full
__device__ int   g_idx_s[BB * SS];   // compact j -> original s
__device__ int   g_rnk_s[BB * SS];   // original s -> compact j or -1
__device__ int   g_cnt_s[BB];
__device__ int   g_idx_t[BB * TT];
__device__ int   g_rnk_t[BB * TT];   // original t -> compact j or -1
__device__ int   g_cnt_t[BB];
__device__ float g_cm [BB * HH];     // (1/T) * sum_t V[b,t,h]

// ---------------------------------------------------------------------------
// Helpers
// ---------------------------------------------------------------------------
__device__ __forceinline__ uint32_t smem_u32(const void* p) {
    uint32_t a;
    asm("{ .reg .u64 t; cvta.to.shared.u64 t, %1; cvt.u32.u64 %0, t; }" : "=r"(a) : "l"(p));
    return a;
}
__device__ __forceinline__ void cp16(uint32_t saddr, const void* g) {
    asm volatile("cp.async.cg.shared.global [%0], [%1], 16;" :: "r"(saddr), "l"(g) : "memory");
}
#define CP_COMMIT() asm volatile("cp.async.commit_group;" ::: "memory")
template <int N>
__device__ __forceinline__ void cp_wait() {
    asm volatile("cp.async.wait_group %0;" :: "n"(N) : "memory");
}
__device__ __forceinline__ void ldsm_x4(uint32_t* r, uint32_t addr) {
    asm volatile("ldmatrix.sync.aligned.m8n8.x4.shared.b16 {%0,%1,%2,%3}, [%4];"
        : "=r"(r[0]), "=r"(r[1]), "=r"(r[2]), "=r"(r[3]) : "r"(addr));
}
__device__ __forceinline__ void mma_bf16(float* c, const uint32_t* a, const uint32_t* b) {
    asm volatile(
        "mma.sync.aligned.m16n8k16.row.col.f32.bf16.bf16.f32 "
        "{%0,%1,%2,%3}, {%4,%5,%6,%7}, {%8,%9}, {%0,%1,%2,%3};"
        : "+f"(c[0]), "+f"(c[1]), "+f"(c[2]), "+f"(c[3])
        : "r"(a[0]), "r"(a[1]), "r"(a[2]), "r"(a[3]), "r"(b[0]), "r"(b[1]));
}
__device__ __forceinline__ void split1(float x, __nv_bfloat16& h, __nv_bfloat16& l) {
    h = __float2bfloat16(x);
    l = __float2bfloat16(x - __bfloat162float(h));
}

// ---------------------------------------------------------------------------
// Per-batch ordered compaction: idx (compact->orig), rnk (orig->compact|-1), cnt.
// 1024 threads, 4 elems each; rows beyond L are ignored.
// ---------------------------------------------------------------------------
__global__ void compact_index(const int* __restrict__ mask, int* __restrict__ idx,
                              int* __restrict__ rnk, int* __restrict__ cnt, int L)
{
    const int b = blockIdx.x;
    const int tid = threadIdx.x;
    const int lane = tid & 31, w = tid >> 5;
    const int* m = mask + (long)b * L;

    int v[4], c = 0;
    #pragma unroll
    for (int i = 0; i < 4; i++) {
        const int p = tid * 4 + i;
        v[i] = (p < L) ? m[p] : 0;
        c += v[i];
    }

    int sc = c;
    #pragma unroll
    for (int o = 1; o < 32; o <<= 1) {
        int t = __shfl_up_sync(0xffffffffu, sc, o);
        if (lane >= o) sc += t;
    }
    __shared__ int ws[32];
    if (lane == 31) ws[w] = sc;
    __syncthreads();
    if (w == 0) {
        int t = ws[lane];
        #pragma unroll
        for (int o = 1; o < 32; o <<= 1) {
            int u = __shfl_up_sync(0xffffffffu, t, o);
            if (lane >= o) t += u;
        }
        ws[lane] = t;
    }
    __syncthreads();
    int base = sc - c + (w ? ws[w - 1] : 0);
    #pragma unroll
    for (int i = 0; i < 4; i++) {
        const int p = tid * 4 + i;
        if (p < L) {
            if (v[i]) { idx[(long)b * L + base] = p; rnk[(long)b * L + p] = base; base++; }
            else      { rnk[(long)b * L + p] = -1; }
        }
    }
    if (tid == 0) cnt[b] = ws[31];
}

// ---------------------------------------------------------------------------
// Fused seq pass: one read of seq -> (a) masked fp32 cat first half,
// (b) split-bf16 gather into compacted seq2 (unmasked rows only).
// ---------------------------------------------------------------------------
__launch_bounds__(256)
__global__ void seq_prep(const float* __restrict__ seq, const int* __restrict__ rnk,
                         float* __restrict__ cat, __nv_bfloat16* __restrict__ out)
{
    const long t = (long)blockIdx.x * 256 + threadIdx.x;
    const long total = (long)BB * SS * (HH / 4);
    if (t >= total) return;
    const long row = t / (HH / 4);
    const int c4 = (int)(t % (HH / 4));
    const int b = (int)(row >> 12);
    const int r = rnk[row];
    float4 v = reinterpret_cast<const float4*>(seq)[row * (HH / 4) + c4];
    if (r < 0) {
        reinterpret_cast<float4*>(cat)[row * (2 * HH / 4) + c4] = make_float4(0, 0, 0, 0);
        return;
    }
    reinterpret_cast<float4*>(cat)[row * (2 * HH / 4) + c4] = v;
    __nv_bfloat16 h0, l0, h1, l1, h2, l2, h3, l3;
    split1(v.x, h0, l0); split1(v.y, h1, l1); split1(v.z, h2, l2); split1(v.w, h3, l3);
    __nv_bfloat16* oh = out + ((long)b * SS + r) * 2L * HH + c4 * 4;
    __nv_bfloat16* ol = oh + HH;
    reinterpret_cast<__nv_bfloat162*>(oh)[0] = __nv_bfloat162(h0, h1);
    reinterpret_cast<__nv_bfloat162*>(oh)[1] = __nv_bfloat162(h2, h3);
    reinterpret_cast<__nv_bfloat162*>(ol)[0] = __nv_bfloat162(l0, l1);
    reinterpret_cast<__nv_bfloat162*>(ol)[1] = __nv_bfloat162(l2, l3);
}

// ---------------------------------------------------------------------------
// tgt gather + split into compacted tgt2 (unmasked rows only).
// ---------------------------------------------------------------------------
__launch_bounds__(256)
__global__ void tgt_prep(const float* __restrict__ tgt, const int* __restrict__ rnk,
                         __nv_bfloat16* __restrict__ out)
{
    const long t = (long)blockIdx.x * 256 + threadIdx.x;
    const long total = (long)BB * TT * (HH / 4);
    if (t >= total) return;
    const long row = t / (HH / 4);
    const int c4 = (int)(t % (HH / 4));
    const int b = (int)(row / TT);
    const int r = rnk[row];
    if (r < 0) return;
    float4 v = reinterpret_cast<const float4*>(tgt)[row * (HH / 4) + c4];
    __nv_bfloat16 h0, l0, h1, l1, h2, l2, h3, l3;
    split1(v.x, h0, l0); split1(v.y, h1, l1); split1(v.z, h2, l2); split1(v.w, h3, l3);
    __nv_bfloat16* oh = out + ((long)b * TT + r) * 2L * HH + c4 * 4;
    __nv_bfloat16* ol = oh + HH;
    reinterpret_cast<__nv_bfloat162*>(oh)[0] = __nv_bfloat162(h0, h1);
    reinterpret_cast<__nv_bfloat162*>(oh)[1] = __nv_bfloat162(h2, h3);
    reinterpret_cast<__nv_bfloat162*>(ol)[0] = __nv_bfloat162(l0, l1);
    reinterpret_cast<__nv_bfloat162*>(ol)[1] = __nv_bfloat162(l2, l3);
}

// ---------------------------------------------------------------------------
// Zero pad rows [cnt, ceil128(cnt)) of both compacted input buffers.
// Zeros propagate: relu(0 @ W) = 0 -> downstream pads all zero.
// grid (BB, 2, 8), 256 threads.
// ---------------------------------------------------------------------------
__global__ void zero_pad(const int* __restrict__ cnt_s, const int* __restrict__ cnt_t,
                         __nv_bfloat16* __restrict__ seq2, __nv_bfloat16* __restrict__ tgt2)
{
    const int b = blockIdx.x;
    int c, L;
    __nv_bfloat16* buf;
    if (blockIdx.y == 0) { c = cnt_s[b]; L = SS; buf = seq2 + (long)b * SS * 2 * HH; }
    else                 { c = cnt_t[b]; L = TT; buf = tgt2 + (long)b * TT * 2 * HH; }
    const int e = min((c + 127) & ~127, L);
    const long nU4 = (long)(e - c) * (2 * HH / 8);
    uint4* base = reinterpret_cast<uint4*>(buf + (long)c * 2 * HH);
    const uint4 z = make_uint4(0, 0, 0, 0);
    for (long i = (long)blockIdx.z * 256 + threadIdx.x; i < nU4; i += (long)gridDim.z * 256)
        base[i] = z;
}

// ---------------------------------------------------------------------------
// fp32 [R,C] -> split bf16 [R,2C]  (W only)
// ---------------------------------------------------------------------------
__launch_bounds__(256)
__global__ void split_plain(const float* __restrict__ in, __nv_bfloat16* __restrict__ out,
                            int R, int C)
{
    const long idx = (long)blockIdx.x * blockDim.x + threadIdx.x;
    const long total = (long)R * C / 4;
    if (idx >= total) return;
    const long row = idx / (C / 4);
    const int c4 = (int)(idx % (C / 4));
    float4 v = reinterpret_cast<const float4*>(in)[idx];
    __nv_bfloat16 h0, l0, h1, l1, h2, l2, h3, l3;
    split1(v.x, h0, l0); split1(v.y, h1, l1); split1(v.z, h2, l2); split1(v.w, h3, l3);
    __nv_bfloat16* oh = out + row * 2L * C + c4 * 4;
    __nv_bfloat16* ol = oh + C;
    reinterpret_cast<__nv_bfloat162*>(oh)[0] = __nv_bfloat162(h0, h1);
    reinterpret_cast<__nv_bfloat162*>(oh)[1] = __nv_bfloat162(h2, h3);
    reinterpret_cast<__nv_bfloat162*>(ol)[0] = __nv_bfloat162(l0, l1);
    reinterpret_cast<__nv_bfloat162*>(ol)[1] = __nv_bfloat162(l2, l3);
}

// ---------------------------------------------------------------------------
// V^T split: O[b,h,t] = split(V[b,t,h]);  O layout [B, H, 2T] (full)
// ---------------------------------------------------------------------------
__global__ void vT_split(const float* __restrict__ V, __nv_bfloat16* __restrict__ O)
{
    __shared__ float tile[32][33];
    const int b = blockIdx.z;
    const int t0 = blockIdx.x * 32, h0 = blockIdx.y * 32;
    const int tx = threadIdx.x, ty = threadIdx.y;
    #pragma unroll
    for (int i = 0; i < 32; i += 8)
        tile[ty + i][tx] = V[((long)b * TT + t0 + ty + i) * HH + h0 + tx];
    __syncthreads();
    #pragma unroll
    for (int i = 0; i < 32; i += 8) {
        const int h = h0 + ty + i, t = t0 + tx;
        __nv_bfloat16 hh, ll;
        split1(tile[tx][ty + i], hh, ll);
        const long base = ((long)b * HH + h) * (2L * TT) + t;
        O[base] = hh; O[base + TT] = ll;
    }
}

// ---------------------------------------------------------------------------
// colmean[b,h] = (1/T) * sum_t V[b,t,h]
// ---------------------------------------------------------------------------
__launch_bounds__(256)
__global__ void colmean_k(const float* __restrict__ V, float* __restrict__ cm)
{
    const int t = blockIdx.x * 256 + threadIdx.x;
    if (t >= BB * HH) return;
    const int b = t / HH, h = t % HH;
    const float* p = V + (long)b * TT * HH + h;
    float s = 0.f;
    #pragma unroll 4
    for (int i = 0; i < TT; i++) s += p[(long)i * HH];
    cm[t] = s * (1.0f / TT);
}

// ---------------------------------------------------------------------------
// Masked seq rows: attn_out = colmean, cat second half = 0.
// ---------------------------------------------------------------------------
__launch_bounds__(256)
__global__ void fill_masked(const int* __restrict__ mask, const float* __restrict__ cm,
                            float* __restrict__ cat, float* __restrict__ attn, int writeAttn)
{
    const long t = (long)blockIdx.x * 256 + threadIdx.x;
    const long total = (long)BB * SS * (HH / 4);
    if (t >= total) return;
    const long row = t / (HH / 4);
    const int c4 = (int)(t % (HH / 4));
    if (mask[row]) return;
    const int b = (int)(row >> 12);
    float4 v = reinterpret_cast<const float4*>(cm)[(long)b * (HH / 4) + c4];
    if (writeAttn)
        reinterpret_cast<float4*>(attn)[row * (HH / 4) + c4] = v;
    reinterpret_cast<float4*>(cat)[row * (2 * HH / 4) + (HH / 4) + c4] = make_float4(0, 0, 0, 0);
}

// ---------------------------------------------------------------------------
// HMMA GEMM (split-bf16 3-term), R7-proven loop. Compaction-aware:
// EPI0: merged seq/tgt @ W^T. seq part: 32 y-blocks/batch, skip past cnt_s.
//       tgt part (y >= ySplit): 4 y-blocks/batch, skip past cnt_t.
// EPI1: logits; skip m0 >= cnt_s[z] and n0 >= cnt_t[z].
// EPI2: P@V full-T; scatter rows via idx with bounds guard.
// ---------------------------------------------------------------------------
template <int EPI>
__launch_bounds__(256)
__global__ void gemm_mma(const __nv_bfloat16* __restrict__ A,
                         const __nv_bfloat16* __restrict__ Bm,
                         long aBatch, long bBatch, int C,
                         float* __restrict__ out0, float* __restrict__ out1,
                         __nv_bfloat16* __restrict__ obf,
                         int writeAttn,
                         const __nv_bfloat16* __restrict__ A2,
                         __nv_bfloat16* __restrict__ obf2, int ySplit,
                         const int* __restrict__ cntp, const int* __restrict__ cnt2p,
                         const int* __restrict__ idxp)
{
    extern __shared__ char smem[];
    const uint32_t sb = smem_u32(smem);

    const int tid = threadIdx.x;
    const int wid = tid >> 5;
    const int lane = tid & 31;

    const int z = blockIdx.z;
    const long Kr = 2L * C;

    const __nv_bfloat16* Ab;
    __nv_bfloat16* obf_sel = obf;
    long orow = 0;
    int m0, cb = SS;
    if (EPI == 0) {
        if ((int)blockIdx.y < ySplit) {
            const int b = blockIdx.y >> 5;              // 32 y-blocks per batch (SS/128)
            m0 = (blockIdx.y & 31) * 128;
            if (m0 >= cntp[b]) return;
            Ab = A + (long)b * aBatch;
            orow = (long)b * SS;
        } else {
            const int yy = (int)blockIdx.y - ySplit;
            const int b = yy >> 2;                      // 4 y-blocks per batch (TT/128)
            m0 = (yy & 3) * 128;
            if (m0 >= cnt2p[b]) return;
            Ab = A2 + (long)b * bBatch;                 // bBatch = tgt2 batch stride (z==0 here)
            orow = (long)b * TT;
            obf_sel = obf2;
        }
    } else if (EPI == 1) {
        m0 = blockIdx.y * 128;
        cb = cntp[z];
        if (m0 >= cb) return;
        if ((int)blockIdx.x * 128 >= cnt2p[z]) return;  // dead logits columns
        Ab = A + (long)z * aBatch;
    } else {
        m0 = blockIdx.y * 128;
        cb = cntp[z];
        if (m0 >= cb) return;
        Ab = A + (long)z * aBatch;
    }
    const int n0 = blockIdx.x * 128;
    const __nv_bfloat16* Bb = Bm + (long)z * ((EPI == 0) ? 0 : bBatch);

    const int kc = C >> 6;
    const int nk = 3 * kc;

    const int vr0 = tid >> 3;
    const int vc16 = (tid & 7) * 16;

#define LDG_STAGE(IT, S)                                                          \
    {                                                                             \
        int _it = (IT);                                                           \
        int _seg = (_it >= 2 * kc) ? 2 : ((_it >= kc) ? 1 : 0);                   \
        int _kl = _it - _seg * kc;                                                \
        long _aC = ((_seg == 1) ? C : 0) + (long)_kl * 64 + (vc16 >> 1);          \
        long _bC = ((_seg == 2) ? C : 0) + (long)_kl * 64 + (vc16 >> 1);          \
        uint32_t _sA = sb + (S) * 32768u;                                         \
        uint32_t _sB = _sA + 16384u;                                              \
        _Pragma("unroll")                                                         \
        for (int i = 0; i < 4; i++) {                                             \
            int r = vr0 + 32 * i;                                                 \
            uint32_t sw = (uint32_t)(r * 128 + (vc16 ^ ((r & 7) << 4)));          \
            cp16(_sA + sw, Ab + (long)(m0 + r) * Kr + _aC);                       \
            cp16(_sB + sw, Bb + (long)(n0 + r) * Kr + _bC);                       \
        }                                                                         \
    }

    LDG_STAGE(0, 0); CP_COMMIT();
    LDG_STAGE(1, 1); CP_COMMIT();

    const int wm = wid & 1;
    const int wn = wid >> 1;

    float acc[4][4][4] = {};

    const int arow = wm * 64 + (lane & 15);
    const int akb = (lane >> 4) * 16;
    const int brow = wn * 32 + (lane & 7) + ((lane >> 4) * 8);
    const int bkb = ((lane >> 3) & 1) * 16;

    for (int it = 0; it < nk; it++) {
        if (it + 1 < nk) cp_wait<1>(); else cp_wait<0>();
        __syncthreads();

        const uint32_t stA = sb + (uint32_t)(it % 3) * 32768u;
        const uint32_t stB = stA + 16384u;

        #pragma unroll
        for (int ks = 0; ks < 4; ks++) {
            uint32_t afr[4][4], bfr[2][4];
            #pragma unroll
            for (int mt = 0; mt < 4; mt++) {
                const int row = arow + mt * 16;
                ldsm_x4(afr[mt], stA + row * 128 + ((ks * 32 + akb) ^ ((row & 7) << 4)));
            }
            #pragma unroll
            for (int ntp = 0; ntp < 2; ntp++) {
                const int row = brow + ntp * 16;
                ldsm_x4(bfr[ntp], stB + row * 128 + ((ks * 32 + bkb) ^ ((row & 7) << 4)));
            }
            #pragma unroll
            for (int mt = 0; mt < 4; mt++)
                #pragma unroll
                for (int nt = 0; nt < 4; nt++)
                    mma_bf16(acc[mt][nt], afr[mt], &bfr[nt >> 1][(nt & 1) * 2]);
        }

        if (it + 2 < nk) { LDG_STAGE(it + 2, (it + 2) % 3); CP_COMMIT(); }
    }

    // ---- epilogue ----
    const int er = wm * 64 + (lane >> 2);
    const int ec = wn * 32 + (lane & 3) * 2;

    if (EPI == 0) {
        const int Nout = gridDim.x * 128;
        #pragma unroll
        for (int mt = 0; mt < 4; mt++)
            #pragma unroll
            for (int nt = 0; nt < 4; nt++)
                #pragma unroll
                for (int h = 0; h < 2; h++) {
                    const long row = orow + m0 + er + mt * 16 + h * 8;
                    const int col = n0 + ec + nt * 8;
                    float x0 = fmaxf(acc[mt][nt][2 * h], 0.f);
                    float x1 = fmaxf(acc[mt][nt][2 * h + 1], 0.f);
                    __nv_bfloat16 h0, l0, h1, l1;
                    split1(x0, h0, l0); split1(x1, h1, l1);
                    __nv_bfloat16* oh = obf_sel + row * 2 * Nout + col;
                    *reinterpret_cast<__nv_bfloat162*>(oh) = __nv_bfloat162(h0, h1);
                    *reinterpret_cast<__nv_bfloat162*>(oh + Nout) = __nv_bfloat162(l0, l1);
                }
    } else if (EPI == 1) {
        #pragma unroll
        for (int mt = 0; mt < 4; mt++)
            #pragma unroll
            for (int nt = 0; nt < 4; nt++)
                #pragma unroll
                for (int h = 0; h < 2; h++) {
                    const int row = m0 + er + mt * 16 + h * 8;
                    const int col = n0 + ec + nt * 8;
                    float2 v = make_float2(acc[mt][nt][2 * h], acc[mt][nt][2 * h + 1]);
                    *reinterpret_cast<float2*>(out0 + ((long)z * SS + row) * TT + col) = v;
                }
    } else {
        const long zb = (long)z * SS;
        #pragma unroll
        for (int mt = 0; mt < 4; mt++)
            #pragma unroll
            for (int h = 0; h < 2; h++) {
                const int local = m0 + er + mt * 16 + h * 8;
                if (local < cb) {
                    const long gs = zb + idxp[zb + local];
                    #pragma unroll
                    for (int nt = 0; nt < 4; nt++) {
                        const int col = n0 + ec + nt * 8;
                        float2 v = make_float2(acc[mt][nt][2 * h], acc[mt][nt][2 * h + 1]);
                        if (writeAttn)
                            *reinterpret_cast<float2*>(out1 + gs * (long)HH + col) = v;
                        *reinterpret_cast<float2*>(out0 + gs * (long)(2 * HH) + HH + col) = v;
                    }
                }
            }
    }
#undef LDG_STAGE
}

// ---------------------------------------------------------------------------
// Softmax over full T with GATHER from compacted logits columns:
// value(t) = rnk_t[t] >= 0 ? logits[row, rnk_t[t]] : 0.0 (exact — masked
// tgt rows give exactly-zero logits). Writes full-T split-bf16 probs.
// ---------------------------------------------------------------------------
__launch_bounds__(128)
__global__ void softmax_split(const float* __restrict__ logits, __nv_bfloat16* __restrict__ P2,
                              const int* __restrict__ cnt_s, const int* __restrict__ rnk_t)
{
    const long row = blockIdx.x;
    const int b = (int)(row >> 12);
    if ((int)(row & (SS - 1)) >= cnt_s[b]) return;
    const float* p = logits + row * TT;
    const int* rb = rnk_t + (long)b * TT;
    const int tid = threadIdx.x;
    const int warp = tid >> 5, lane = tid & 31;

    float v[4];
    #pragma unroll
    for (int i = 0; i < 4; i++) {
        const int r = rb[tid + 128 * i];
        v[i] = (r >= 0) ? p[r] : 0.0f;
    }

    float mx = fmaxf(fmaxf(v[0], v[1]), fmaxf(v[2], v[3]));
    #pragma unroll
    for (int o = 16; o > 0; o >>= 1) mx = fmaxf(mx, __shfl_xor_sync(0xffffffffu, mx, o));
    __shared__ float smx[4];
    if (lane == 0) smx[warp] = mx;
    __syncthreads();
    mx = fmaxf(fmaxf(smx[0], smx[1]), fmaxf(smx[2], smx[3]));

    float sum = 0.f;
    #pragma unroll
    for (int i = 0; i < 4; i++) { v[i] = __expf(v[i] - mx); sum += v[i]; }
    #pragma unroll
    for (int o = 16; o > 0; o >>= 1) sum += __shfl_xor_sync(0xffffffffu, sum, o);
    __shared__ float ssum[4];
    if (lane == 0) ssum[warp] = sum;
    __syncthreads();
    const float inv = 1.0f / (ssum[0] + ssum[1] + ssum[2] + ssum[3]);

    __nv_bfloat16* out = P2 + row * 2L * TT;
    #pragma unroll
    for (int i = 0; i < 4; i++) {
        const int idx = tid + 128 * i;
        __nv_bfloat16 h, l;
        split1(v[i] * inv, h, l);
        out[idx] = h; out[TT + idx] = l;
    }
}

// ---------------------------------------------------------------------------

extern "C" void kernel_launch(void* const* d_in, const int* in_sizes, int n_in,
                              void* d_out, int out_size)
{
    const float* seq   = (const float*)d_in[0];
    const int*   smask = (const int*)d_in[1];
    const float* tgt   = (const float*)d_in[2];
    const int*   tmask = (const int*)d_in[3];
    const float* W     = (const float*)d_in[4];
    float* out = (float*)d_out;

    __nv_bfloat16 *p_seq2, *p_tgt2, *p_W2, *p_seqt2, *p_tgtt2, *p_probs2, *p_vT2;
    float *p_logits, *p_cm;
    int *p_idx_s, *p_rnk_s, *p_cnt_s, *p_idx_t, *p_rnk_t, *p_cnt_t;
    cudaGetSymbolAddress((void**)&p_seq2, g_seq2);
    cudaGetSymbolAddress((void**)&p_tgt2, g_tgt2);
    cudaGetSymbolAddress((void**)&p_W2, g_W2);
    cudaGetSymbolAddress((void**)&p_seqt2, g_seqt2);
    cudaGetSymbolAddress((void**)&p_tgtt2, g_tgtt2);
    cudaGetSymbolAddress((void**)&p_logits, g_logits);
    cudaGetSymbolAddress((void**)&p_probs2, g_probs2);
    cudaGetSymbolAddress((void**)&p_vT2, g_vT2);
    cudaGetSymbolAddress((void**)&p_idx_s, g_idx_s);
    cudaGetSymbolAddress((void**)&p_rnk_s, g_rnk_s);
    cudaGetSymbolAddress((void**)&p_cnt_s, g_cnt_s);
    cudaGetSymbolAddress((void**)&p_idx_t, g_idx_t);
    cudaGetSymbolAddress((void**)&p_rnk_t, g_rnk_t);
    cudaGetSymbolAddress((void**)&p_cnt_t, g_cnt_t);
    cudaGetSymbolAddress((void**)&p_cm, g_cm);

    const int write_attn = (out_size >= BB * SS * 3 * HH) ? 1 : 0;
    float* out_attn = out + (size_t)BB * SS * 2 * HH;

    const int SMEM_DYN = 3 * 32768;
    cudaFuncSetAttribute(gemm_mma<0>, cudaFuncAttributeMaxDynamicSharedMemorySize, SMEM_DYN);
    cudaFuncSetAttribute(gemm_mma<1>, cudaFuncAttributeMaxDynamicSharedMemorySize, SMEM_DYN);
    cudaFuncSetAttribute(gemm_mma<2>, cudaFuncAttributeMaxDynamicSharedMemorySize, SMEM_DYN);

    const int NCHUNK_S = (BB * SS * (HH / 4) + 255) / 256;
    const int NCHUNK_T = (BB * TT * (HH / 4) + 255) / 256;

    // 0) compaction + operand prep
    compact_index<<<BB, 1024>>>(smask, p_idx_s, p_rnk_s, p_cnt_s, SS);
    compact_index<<<BB, 1024>>>(tmask, p_idx_t, p_rnk_t, p_cnt_t, TT);
    seq_prep<<<NCHUNK_S, 256>>>(seq, p_rnk_s, out, p_seq2);
    tgt_prep<<<NCHUNK_T, 256>>>(tgt, p_rnk_t, p_tgt2);
    zero_pad<<<dim3(BB, 2, 8), 256>>>(p_cnt_s, p_cnt_t, p_seq2, p_tgt2);
    split_plain<<<(HH * HH / 4 + 255) / 256, 256>>>(W, p_W2, HH, HH);
    vT_split<<<dim3(TT / 32, HH / 32, BB), dim3(32, 8)>>>(tgt, p_vT2);
    colmean_k<<<(BB * HH + 255) / 256, 256>>>(tgt, p_cm);

    // 1+2 merged) seq_t AND tgt_t = relu(X @ W^T), both compacted
    const int Y_SEQ = (BB * SS) / 128;   // 256
    const int Y_TGT = (BB * TT) / 128;   // 32
    gemm_mma<0><<<dim3(HH / 128, Y_SEQ + Y_TGT, 1), 256, SMEM_DYN>>>(
        p_seq2, p_W2, (long)SS * 2 * HH, (long)TT * 2 * HH, HH,
        nullptr, nullptr, p_seqt2, 0,
        p_tgt2, p_tgtt2, Y_SEQ, p_cnt_s, p_cnt_t, nullptr);

    // 3) logits = seq_t @ tgt_t^T (rows AND cols compacted)
    gemm_mma<1><<<dim3(TT / 128, SS / 128, BB), 256, SMEM_DYN>>>(
        p_seqt2, p_tgtt2, (long)SS * 2 * HH, (long)TT * 2 * HH, HH,
        p_logits, nullptr, nullptr, 0, nullptr, nullptr, 1 << 30,
        p_cnt_s, p_cnt_t, nullptr);

    // 4) softmax: gather compacted logits via rnk_t, write full-T probs
    softmax_split<<<BB * SS, 128>>>(p_logits, p_probs2, p_cnt_s, p_rnk_t);

    // 5) attn_out = P @ V (full T), scatter epilogue to original seq rows
    gemm_mma<2><<<dim3(HH / 128, SS / 128, BB), 256, SMEM_DYN>>>(
        p_probs2, p_vT2, (long)SS * 2 * TT, (long)HH * 2 * TT, TT,
        out, out_attn, nullptr, write_attn, nullptr, nullptr, 1 << 30,
        p_cnt_s, nullptr, p_idx_s);

    // 6) masked seq rows: attn = colmean(V), cat second half = 0
    fill_masked<<<NCHUNK_S, 256>>>(smask, p_cm, out, out_attn, write_attn);
}

// round 12
// speedup vs baseline: 1.6026x; 1.0378x over previous
#include <cuda_runtime.h>
#include <cuda_bf16.h>
#include <cstdint>

#define BB 8
#define SS 4096
#define TT 512
#define HH 768

// ---------------------------------------------------------------------------
// Scratch. Split bf16: [R, 2C], hi in [0,C), lo in [C,2C).
// seq-side and tgt-side buffers COMPACTED per batch (unmasked rows first).
// probs/vT2 are compacted along t as well (K of GEMM5).
// ---------------------------------------------------------------------------
__device__ __align__(16) __nv_bfloat16 g_seq2 [(size_t)BB * SS * 2 * HH];
__device__ __align__(16) __nv_bfloat16 g_tgt2 [(size_t)BB * TT * 2 * HH];
__device__ __align__(16) __nv_bfloat16 g_W2   [(size_t)HH * 2 * HH];
__device__ __align__(16) __nv_bfloat16 g_seqt2[(size_t)BB * SS * 2 * HH];
__device__ __align__(16) __nv_bfloat16 g_tgtt2[(size_t)BB * TT * 2 * HH];
__device__ __align__(16) float         g_logits[(size_t)BB * SS * TT];
__device__ __align__(16) __nv_bfloat16 g_probs2[(size_t)BB * SS * 2 * TT]; // compact rows+cols
__device__ __align__(16) __nv_bfloat16 g_vT2  [(size_t)BB * HH * 2 * TT];  // compact t cols
__device__ int   g_idx_s[BB * SS];
__device__ int   g_rnk_s[BB * SS];
__device__ int   g_cnt_s[BB];
__device__ int   g_idx_t[BB * TT];
__device__ int   g_rnk_t[BB * TT];
__device__ int   g_cnt_t[BB];
__device__ float g_cm [BB * HH];    // (1/T)*sum_all_t V
__device__ float g_vm [BB * HH];    // sum_masked_t V
__device__ float g_c  [BB * SS];    // per compact seq row: masked-t prob

// ---------------------------------------------------------------------------
// Helpers
// ---------------------------------------------------------------------------
__device__ __forceinline__ uint32_t smem_u32(const void* p) {
    uint32_t a;
    asm("{ .reg .u64 t; cvta.to.shared.u64 t, %1; cvt.u32.u64 %0, t; }" : "=r"(a) : "l"(p));
    return a;
}
__device__ __forceinline__ void cp16(uint32_t saddr, const void* g) {
    asm volatile("cp.async.cg.shared.global [%0], [%1], 16;" :: "r"(saddr), "l"(g) : "memory");
}
#define CP_COMMIT() asm volatile("cp.async.commit_group;" ::: "memory")
template <int N>
__device__ __forceinline__ void cp_wait() {
    asm volatile("cp.async.wait_group %0;" :: "n"(N) : "memory");
}
__device__ __forceinline__ void ldsm_x4(uint32_t* r, uint32_t addr) {
    asm volatile("ldmatrix.sync.aligned.m8n8.x4.shared.b16 {%0,%1,%2,%3}, [%4];"
        : "=r"(r[0]), "=r"(r[1]), "=r"(r[2]), "=r"(r[3]) : "r"(addr));
}
__device__ __forceinline__ void mma_bf16(float* c, const uint32_t* a, const uint32_t* b) {
    asm volatile(
        "mma.sync.aligned.m16n8k16.row.col.f32.bf16.bf16.f32 "
        "{%0,%1,%2,%3}, {%4,%5,%6,%7}, {%8,%9}, {%0,%1,%2,%3};"
        : "+f"(c[0]), "+f"(c[1]), "+f"(c[2]), "+f"(c[3])
        : "r"(a[0]), "r"(a[1]), "r"(a[2]), "r"(a[3]), "r"(b[0]), "r"(b[1]));
}
__device__ __forceinline__ void split1(float x, __nv_bfloat16& h, __nv_bfloat16& l) {
    h = __float2bfloat16(x);
    l = __float2bfloat16(x - __bfloat162float(h));
}

// ---------------------------------------------------------------------------
// Per-batch ordered compaction: idx (compact->orig), rnk (orig->compact|-1), cnt.
// ---------------------------------------------------------------------------
__global__ void compact_index(const int* __restrict__ mask, int* __restrict__ idx,
                              int* __restrict__ rnk, int* __restrict__ cnt, int L)
{
    const int b = blockIdx.x;
    const int tid = threadIdx.x;
    const int lane = tid & 31, w = tid >> 5;
    const int* m = mask + (long)b * L;

    int v[4], c = 0;
    #pragma unroll
    for (int i = 0; i < 4; i++) {
        const int p = tid * 4 + i;
        v[i] = (p < L) ? m[p] : 0;
        c += v[i];
    }
    int sc = c;
    #pragma unroll
    for (int o = 1; o < 32; o <<= 1) {
        int t = __shfl_up_sync(0xffffffffu, sc, o);
        if (lane >= o) sc += t;
    }
    __shared__ int ws[32];
    if (lane == 31) ws[w] = sc;
    __syncthreads();
    if (w == 0) {
        int t = ws[lane];
        #pragma unroll
        for (int o = 1; o < 32; o <<= 1) {
            int u = __shfl_up_sync(0xffffffffu, t, o);
            if (lane >= o) t += u;
        }
        ws[lane] = t;
    }
    __syncthreads();
    int base = sc - c + (w ? ws[w - 1] : 0);
    #pragma unroll
    for (int i = 0; i < 4; i++) {
        const int p = tid * 4 + i;
        if (p < L) {
            if (v[i]) { idx[(long)b * L + base] = p; rnk[(long)b * L + p] = base; base++; }
            else      { rnk[(long)b * L + p] = -1; }
        }
    }
    if (tid == 0) cnt[b] = ws[31];
}

// ---------------------------------------------------------------------------
// Fused seq pass: one read -> masked fp32 cat first half + compacted split seq2.
// ---------------------------------------------------------------------------
__launch_bounds__(256)
__global__ void seq_prep(const float* __restrict__ seq, const int* __restrict__ rnk,
                         float* __restrict__ cat, __nv_bfloat16* __restrict__ out)
{
    const long t = (long)blockIdx.x * 256 + threadIdx.x;
    const long total = (long)BB * SS * (HH / 4);
    if (t >= total) return;
    const long row = t / (HH / 4);
    const int c4 = (int)(t % (HH / 4));
    const int b = (int)(row >> 12);
    const int r = rnk[row];
    float4 v = reinterpret_cast<const float4*>(seq)[row * (HH / 4) + c4];
    if (r < 0) {
        reinterpret_cast<float4*>(cat)[row * (2 * HH / 4) + c4] = make_float4(0, 0, 0, 0);
        return;
    }
    reinterpret_cast<float4*>(cat)[row * (2 * HH / 4) + c4] = v;
    __nv_bfloat16 h0, l0, h1, l1, h2, l2, h3, l3;
    split1(v.x, h0, l0); split1(v.y, h1, l1); split1(v.z, h2, l2); split1(v.w, h3, l3);
    __nv_bfloat16* oh = out + ((long)b * SS + r) * 2L * HH + c4 * 4;
    __nv_bfloat16* ol = oh + HH;
    reinterpret_cast<__nv_bfloat162*>(oh)[0] = __nv_bfloat162(h0, h1);
    reinterpret_cast<__nv_bfloat162*>(oh)[1] = __nv_bfloat162(h2, h3);
    reinterpret_cast<__nv_bfloat162*>(ol)[0] = __nv_bfloat162(l0, l1);
    reinterpret_cast<__nv_bfloat162*>(ol)[1] = __nv_bfloat162(l2, l3);
}

// ---------------------------------------------------------------------------
// Fused tgt pass: one read of V tile -> compacted tgt2 (row-major) AND
// compacted transposed vT2 [B, H, 2T-compact].
// ---------------------------------------------------------------------------
__global__ void tgtv_prep(const float* __restrict__ V, const int* __restrict__ rnk,
                          __nv_bfloat16* __restrict__ tgt2, __nv_bfloat16* __restrict__ vT2)
{
    __shared__ float tile[32][33];
    const int b = blockIdx.z;
    const int t0 = blockIdx.x * 32, h0 = blockIdx.y * 32;
    const int tx = threadIdx.x, ty = threadIdx.y;  // 32 x 8
    #pragma unroll
    for (int i = 0; i < 32; i += 8)
        tile[ty + i][tx] = V[((long)b * TT + t0 + ty + i) * HH + h0 + tx];
    __syncthreads();
    // vT2: thread (tx,ty+i) handles (h = h0+ty+i, t = t0+tx)
    #pragma unroll
    for (int i = 0; i < 32; i += 8) {
        const int h = h0 + ty + i, t = t0 + tx;
        const int j = rnk[(long)b * TT + t];
        if (j >= 0) {
            __nv_bfloat16 hh, ll;
            split1(tile[tx][ty + i], hh, ll);
            const long base = ((long)b * HH + h) * (2L * TT) + j;
            vT2[base] = hh; vT2[base + TT] = ll;
        }
    }
    // tgt2: thread (tx,ty+i) handles (t = t0+ty+i, h = h0+tx)
    #pragma unroll
    for (int i = 0; i < 32; i += 8) {
        const int t = t0 + ty + i;
        const int j = rnk[(long)b * TT + t];
        if (j >= 0) {
            __nv_bfloat16 hh, ll;
            split1(tile[ty + i][tx], hh, ll);
            __nv_bfloat16* o = tgt2 + ((long)b * TT + j) * 2L * HH + h0 + tx;
            o[0] = hh; o[HH] = ll;
        }
    }
}

// ---------------------------------------------------------------------------
// Zero pads: y=0 seq2 rows, y=1 tgt2 rows, y=2 vT2 pad columns.
// ---------------------------------------------------------------------------
__global__ void zero_pad(const int* __restrict__ cnt_s, const int* __restrict__ cnt_t,
                         __nv_bfloat16* __restrict__ seq2, __nv_bfloat16* __restrict__ tgt2,
                         __nv_bfloat16* __restrict__ vT2)
{
    const int b = blockIdx.x;
    if (blockIdx.y == 2) {
        const int c = cnt_t[b];
        const int kpad = (c + 127) & ~127;          // generous pad
        const int padw = min(kpad, TT) - c;
        if (padw <= 0) return;
        const long total = (long)HH * 2 * padw;
        for (long i = (long)blockIdx.z * 256 + threadIdx.x; i < total;
             i += (long)gridDim.z * 256) {
            const int h = (int)(i / (2 * padw));
            const int r = (int)(i % (2 * padw));
            const int sl = r / padw, off = r % padw;
            vT2[((long)b * HH + h) * (2L * TT) + (long)sl * TT + c + off] = __nv_bfloat16(0.f);
        }
        return;
    }
    int c, L;
    __nv_bfloat16* buf;
    if (blockIdx.y == 0) { c = cnt_s[b]; L = SS; buf = seq2 + (long)b * SS * 2 * HH; }
    else                 { c = cnt_t[b]; L = TT; buf = tgt2 + (long)b * TT * 2 * HH; }
    const int e = min((c + 127) & ~127, L);
    const long nU4 = (long)(e - c) * (2 * HH / 8);
    uint4* base = reinterpret_cast<uint4*>(buf + (long)c * 2 * HH);
    const uint4 z = make_uint4(0, 0, 0, 0);
    for (long i = (long)blockIdx.z * 256 + threadIdx.x; i < nU4; i += (long)gridDim.z * 256)
        base[i] = z;
}

// ---------------------------------------------------------------------------
// W: fp32 -> split bf16
// ---------------------------------------------------------------------------
__launch_bounds__(256)
__global__ void split_plain(const float* __restrict__ in, __nv_bfloat16* __restrict__ out,
                            int R, int C)
{
    const long idx = (long)blockIdx.x * blockDim.x + threadIdx.x;
    const long total = (long)R * C / 4;
    if (idx >= total) return;
    const long row = idx / (C / 4);
    const int c4 = (int)(idx % (C / 4));
    float4 v = reinterpret_cast<const float4*>(in)[idx];
    __nv_bfloat16 h0, l0, h1, l1, h2, l2, h3, l3;
    split1(v.x, h0, l0); split1(v.y, h1, l1); split1(v.z, h2, l2); split1(v.w, h3, l3);
    __nv_bfloat16* oh = out + row * 2L * C + c4 * 4;
    __nv_bfloat16* ol = oh + C;
    reinterpret_cast<__nv_bfloat162*>(oh)[0] = __nv_bfloat162(h0, h1);
    reinterpret_cast<__nv_bfloat162*>(oh)[1] = __nv_bfloat162(h2, h3);
    reinterpret_cast<__nv_bfloat162*>(ol)[0] = __nv_bfloat162(l0, l1);
    reinterpret_cast<__nv_bfloat162*>(ol)[1] = __nv_bfloat162(l2, l3);
}

// ---------------------------------------------------------------------------
// colstat: cm = (1/T) sum_all V;  vm = sum over MASKED t of V.
// ---------------------------------------------------------------------------
__launch_bounds__(256)
__global__ void colstat(const float* __restrict__ V, const int* __restrict__ tmask,
                        float* __restrict__ cm, float* __restrict__ vm)
{
    const int t = blockIdx.x * 256 + threadIdx.x;
    if (t >= BB * HH) return;
    const int b = t / HH, h = t % HH;
    const float* p = V + (long)b * TT * HH + h;
    const int* m = tmask + (long)b * TT;
    float sa = 0.f, sm_ = 0.f;
    #pragma unroll 4
    for (int i = 0; i < TT; i++) {
        const float x = p[(long)i * HH];
        sa += x;
        if (!m[i]) sm_ += x;
    }
    cm[t] = sa * (1.0f / TT);
    vm[t] = sm_;
}

// ---------------------------------------------------------------------------
// Masked seq rows: attn_out = colmean, cat second half = 0.
// ---------------------------------------------------------------------------
__launch_bounds__(256)
__global__ void fill_masked(const int* __restrict__ mask, const float* __restrict__ cm,
                            float* __restrict__ cat, float* __restrict__ attn, int writeAttn)
{
    const long t = (long)blockIdx.x * 256 + threadIdx.x;
    const long total = (long)BB * SS * (HH / 4);
    if (t >= total) return;
    const long row = t / (HH / 4);
    const int c4 = (int)(t % (HH / 4));
    if (mask[row]) return;
    const int b = (int)(row >> 12);
    float4 v = reinterpret_cast<const float4*>(cm)[(long)b * (HH / 4) + c4];
    if (writeAttn)
        reinterpret_cast<float4*>(attn)[row * (HH / 4) + c4] = v;
    reinterpret_cast<float4*>(cat)[row * (2 * HH / 4) + (HH / 4) + c4] = make_float4(0, 0, 0, 0);
}

// ---------------------------------------------------------------------------
// HMMA GEMM (split-bf16 3-term). Compaction-aware.
// EPI2: K dimension = ceil64(cnt_t[z]) (compacted probs/vT2), and the
// epilogue adds the rank-1 masked-t correction c_row * vm[b,col].
// ---------------------------------------------------------------------------
template <int EPI>
__launch_bounds__(256)
__global__ void gemm_mma(const __nv_bfloat16* __restrict__ A,
                         const __nv_bfloat16* __restrict__ Bm,
                         long aBatch, long bBatch, int C,
                         float* __restrict__ out0, float* __restrict__ out1,
                         __nv_bfloat16* __restrict__ obf,
                         int writeAttn,
                         const __nv_bfloat16* __restrict__ A2,
                         __nv_bfloat16* __restrict__ obf2, int ySplit,
                         const int* __restrict__ cntp, const int* __restrict__ cnt2p,
                         const int* __restrict__ idxp,
                         const float* __restrict__ cvec, const float* __restrict__ vmsum)
{
    extern __shared__ char smem[];
    const uint32_t sb = smem_u32(smem);

    const int tid = threadIdx.x;
    const int wid = tid >> 5;
    const int lane = tid & 31;

    const int z = blockIdx.z;
    const long Kr = 2L * C;

    const __nv_bfloat16* Ab;
    __nv_bfloat16* obf_sel = obf;
    long orow = 0;
    int m0, cb = SS;
    if (EPI == 0) {
        if ((int)blockIdx.y < ySplit) {
            const int b = blockIdx.y >> 5;
            m0 = (blockIdx.y & 31) * 128;
            if (m0 >= cntp[b]) return;
            Ab = A + (long)b * aBatch;
            orow = (long)b * SS;
        } else {
            const int yy = (int)blockIdx.y - ySplit;
            const int b = yy >> 2;
            m0 = (yy & 3) * 128;
            if (m0 >= cnt2p[b]) return;
            Ab = A2 + (long)b * bBatch;
            orow = (long)b * TT;
            obf_sel = obf2;
        }
    } else if (EPI == 1) {
        m0 = blockIdx.y * 128;
        cb = cntp[z];
        if (m0 >= cb) return;
        if ((int)blockIdx.x * 128 >= cnt2p[z]) return;
        Ab = A + (long)z * aBatch;
    } else {
        m0 = blockIdx.y * 128;
        cb = cntp[z];
        if (m0 >= cb) return;
        Ab = A + (long)z * aBatch;
    }
    const int n0 = blockIdx.x * 128;
    const __nv_bfloat16* Bb = Bm + (long)z * ((EPI == 0) ? 0 : bBatch);

    int kc;
    if (EPI == 2) kc = (cnt2p[z] + 63) >> 6;   // compacted K (probs/vT2 cols)
    else          kc = C >> 6;
    const int nk = 3 * kc;

    const int vr0 = tid >> 3;
    const int vc16 = (tid & 7) * 16;

#define LDG_STAGE(IT, S)                                                          \
    {                                                                             \
        int _it = (IT);                                                           \
        int _seg = (_it >= 2 * kc) ? 2 : ((_it >= kc) ? 1 : 0);                   \
        int _kl = _it - _seg * kc;                                                \
        long _aC = ((_seg == 1) ? C : 0) + (long)_kl * 64 + (vc16 >> 1);          \
        long _bC = ((_seg == 2) ? C : 0) + (long)_kl * 64 + (vc16 >> 1);          \
        uint32_t _sA = sb + (S) * 32768u;                                         \
        uint32_t _sB = _sA + 16384u;                                              \
        _Pragma("unroll")                                                         \
        for (int i = 0; i < 4; i++) {                                             \
            int r = vr0 + 32 * i;                                                 \
            uint32_t sw = (uint32_t)(r * 128 + (vc16 ^ ((r & 7) << 4)));          \
            cp16(_sA + sw, Ab + (long)(m0 + r) * Kr + _aC);                       \
            cp16(_sB + sw, Bb + (long)(n0 + r) * Kr + _bC);                       \
        }                                                                         \
    }

    LDG_STAGE(0, 0); CP_COMMIT();
    LDG_STAGE(1, 1); CP_COMMIT();

    const int wm = wid & 1;
    const int wn = wid >> 1;

    float acc[4][4][4] = {};

    const int arow = wm * 64 + (lane & 15);
    const int akb = (lane >> 4) * 16;
    const int brow = wn * 32 + (lane & 7) + ((lane >> 4) * 8);
    const int bkb = ((lane >> 3) & 1) * 16;

    for (int it = 0; it < nk; it++) {
        if (it + 1 < nk) cp_wait<1>(); else cp_wait<0>();
        __syncthreads();

        const uint32_t stA = sb + (uint32_t)(it % 3) * 32768u;
        const uint32_t stB = stA + 16384u;

        #pragma unroll
        for (int ks = 0; ks < 4; ks++) {
            uint32_t afr[4][4], bfr[2][4];
            #pragma unroll
            for (int mt = 0; mt < 4; mt++) {
                const int row = arow + mt * 16;
                ldsm_x4(afr[mt], stA + row * 128 + ((ks * 32 + akb) ^ ((row & 7) << 4)));
            }
            #pragma unroll
            for (int ntp = 0; ntp < 2; ntp++) {
                const int row = brow + ntp * 16;
                ldsm_x4(bfr[ntp], stB + row * 128 + ((ks * 32 + bkb) ^ ((row & 7) << 4)));
            }
            #pragma unroll
            for (int mt = 0; mt < 4; mt++)
                #pragma unroll
                for (int nt = 0; nt < 4; nt++)
                    mma_bf16(acc[mt][nt], afr[mt], &bfr[nt >> 1][(nt & 1) * 2]);
        }

        if (it + 2 < nk) { LDG_STAGE(it + 2, (it + 2) % 3); CP_COMMIT(); }
    }

    // ---- epilogue ----
    const int er = wm * 64 + (lane >> 2);
    const int ec = wn * 32 + (lane & 3) * 2;

    if (EPI == 0) {
        const int Nout = gridDim.x * 128;
        #pragma unroll
        for (int mt = 0; mt < 4; mt++)
            #pragma unroll
            for (int nt = 0; nt < 4; nt++)
                #pragma unroll
                for (int h = 0; h < 2; h++) {
                    const long row = orow + m0 + er + mt * 16 + h * 8;
                    const int col = n0 + ec + nt * 8;
                    float x0 = fmaxf(acc[mt][nt][2 * h], 0.f);
                    float x1 = fmaxf(acc[mt][nt][2 * h + 1], 0.f);
                    __nv_bfloat16 h0, l0, h1, l1;
                    split1(x0, h0, l0); split1(x1, h1, l1);
                    __nv_bfloat16* oh = obf_sel + row * 2 * Nout + col;
                    *reinterpret_cast<__nv_bfloat162*>(oh) = __nv_bfloat162(h0, h1);
                    *reinterpret_cast<__nv_bfloat162*>(oh + Nout) = __nv_bfloat162(l0, l1);
                }
    } else if (EPI == 1) {
        #pragma unroll
        for (int mt = 0; mt < 4; mt++)
            #pragma unroll
            for (int nt = 0; nt < 4; nt++)
                #pragma unroll
                for (int h = 0; h < 2; h++) {
                    const int row = m0 + er + mt * 16 + h * 8;
                    const int col = n0 + ec + nt * 8;
                    float2 v = make_float2(acc[mt][nt][2 * h], acc[mt][nt][2 * h + 1]);
                    *reinterpret_cast<float2*>(out0 + ((long)z * SS + row) * TT + col) = v;
                }
    } else {
        const long zb = (long)z * SS;
        #pragma unroll
        for (int mt = 0; mt < 4; mt++)
            #pragma unroll
            for (int h = 0; h < 2; h++) {
                const int local = m0 + er + mt * 16 + h * 8;
                if (local < cb) {
                    const float cr = cvec[zb + local];
                    const long gs = zb + idxp[zb + local];
                    #pragma unroll
                    for (int nt = 0; nt < 4; nt++) {
                        const int col = n0 + ec + nt * 8;
                        const float2 w = *reinterpret_cast<const float2*>(
                            vmsum + (long)z * HH + col);
                        float2 v = make_float2(acc[mt][nt][2 * h] + cr * w.x,
                                               acc[mt][nt][2 * h + 1] + cr * w.y);
                        if (writeAttn)
                            *reinterpret_cast<float2*>(out1 + gs * (long)HH + col) = v;
                        *reinterpret_cast<float2*>(out0 + gs * (long)(2 * HH) + HH + col) = v;
                    }
                }
            }
    }
#undef LDG_STAGE
}

// ---------------------------------------------------------------------------
// Softmax on COMPACTED logits. Denominator includes (T-ct) masked terms of
// exp(-mx). Writes compacted split-bf16 probs (zero-padded to ceil64) and the
// per-row masked-t probability c = exp(-mx)/sum.
// ---------------------------------------------------------------------------
__launch_bounds__(128)
__global__ void softmax_c(const float* __restrict__ logits, __nv_bfloat16* __restrict__ P2,
                          float* __restrict__ cvec,
                          const int* __restrict__ cnt_s, const int* __restrict__ cnt_t)
{
    const long row = blockIdx.x;
    const int b = (int)(row >> 12);
    if ((int)(row & (SS - 1)) >= cnt_s[b]) return;
    const int ct = cnt_t[b];
    const int kpad = (ct + 63) & ~63;
    const float* p = logits + row * TT;
    const int tid = threadIdx.x;
    const int warp = tid >> 5, lane = tid & 31;

    float v[4];
    #pragma unroll
    for (int i = 0; i < 4; i++) {
        const int j = tid + 128 * i;
        v[i] = (j < ct) ? p[j] : -1e30f;
    }

    float mx = fmaxf(fmaxf(v[0], v[1]), fmaxf(v[2], v[3]));
    #pragma unroll
    for (int o = 16; o > 0; o >>= 1) mx = fmaxf(mx, __shfl_xor_sync(0xffffffffu, mx, o));
    __shared__ float smx[4];
    if (lane == 0) smx[warp] = mx;
    __syncthreads();
    mx = fmaxf(fmaxf(smx[0], smx[1]), fmaxf(smx[2], smx[3]));
    if (ct < TT) mx = fmaxf(mx, 0.0f);   // masked-t logits are exactly 0

    float sum = 0.f;
    #pragma unroll
    for (int i = 0; i < 4; i++) {
        const int j = tid + 128 * i;
        if (j < ct) { v[i] = __expf(v[i] - mx); sum += v[i]; }
    }
    #pragma unroll
    for (int o = 16; o > 0; o >>= 1) sum += __shfl_xor_sync(0xffffffffu, sum, o);
    __shared__ float ssum[4];
    if (lane == 0) ssum[warp] = sum;
    __syncthreads();
    const float em = __expf(-mx);
    const float inv = 1.0f / (ssum[0] + ssum[1] + ssum[2] + ssum[3] + (float)(TT - ct) * em);

    if (tid == 0) cvec[row] = em * inv;

    __nv_bfloat16* out = P2 + row * 2L * TT;
    #pragma unroll
    for (int i = 0; i < 4; i++) {
        const int j = tid + 128 * i;
        if (j < ct) {
            __nv_bfloat16 h, l;
            split1(v[i] * inv, h, l);
            out[j] = h; out[TT + j] = l;
        } else if (j < kpad) {
            out[j] = __nv_bfloat16(0.f); out[TT + j] = __nv_bfloat16(0.f);
        }
    }
}

// ---------------------------------------------------------------------------

extern "C" void kernel_launch(void* const* d_in, const int* in_sizes, int n_in,
                              void* d_out, int out_size)
{
    const float* seq   = (const float*)d_in[0];
    const int*   smask = (const int*)d_in[1];
    const float* tgt   = (const float*)d_in[2];
    const int*   tmask = (const int*)d_in[3];
    const float* W     = (const float*)d_in[4];
    float* out = (float*)d_out;

    __nv_bfloat16 *p_seq2, *p_tgt2, *p_W2, *p_seqt2, *p_tgtt2, *p_probs2, *p_vT2;
    float *p_logits, *p_cm, *p_vm, *p_c;
    int *p_idx_s, *p_rnk_s, *p_cnt_s, *p_idx_t, *p_rnk_t, *p_cnt_t;
    cudaGetSymbolAddress((void**)&p_seq2, g_seq2);
    cudaGetSymbolAddress((void**)&p_tgt2, g_tgt2);
    cudaGetSymbolAddress((void**)&p_W2, g_W2);
    cudaGetSymbolAddress((void**)&p_seqt2, g_seqt2);
    cudaGetSymbolAddress((void**)&p_tgtt2, g_tgtt2);
    cudaGetSymbolAddress((void**)&p_logits, g_logits);
    cudaGetSymbolAddress((void**)&p_probs2, g_probs2);
    cudaGetSymbolAddress((void**)&p_vT2, g_vT2);
    cudaGetSymbolAddress((void**)&p_idx_s, g_idx_s);
    cudaGetSymbolAddress((void**)&p_rnk_s, g_rnk_s);
    cudaGetSymbolAddress((void**)&p_cnt_s, g_cnt_s);
    cudaGetSymbolAddress((void**)&p_idx_t, g_idx_t);
    cudaGetSymbolAddress((void**)&p_rnk_t, g_rnk_t);
    cudaGetSymbolAddress((void**)&p_cnt_t, g_cnt_t);
    cudaGetSymbolAddress((void**)&p_cm, g_cm);
    cudaGetSymbolAddress((void**)&p_vm, g_vm);
    cudaGetSymbolAddress((void**)&p_c, g_c);

    const int write_attn = (out_size >= BB * SS * 3 * HH) ? 1 : 0;
    float* out_attn = out + (size_t)BB * SS * 2 * HH;

    const int SMEM_DYN = 3 * 32768;
    cudaFuncSetAttribute(gemm_mma<0>, cudaFuncAttributeMaxDynamicSharedMemorySize, SMEM_DYN);
    cudaFuncSetAttribute(gemm_mma<1>, cudaFuncAttributeMaxDynamicSharedMemorySize, SMEM_DYN);
    cudaFuncSetAttribute(gemm_mma<2>, cudaFuncAttributeMaxDynamicSharedMemorySize, SMEM_DYN);

    const int NCHUNK_S = (BB * SS * (HH / 4) + 255) / 256;

    // 0) compaction + operand prep
    compact_index<<<BB, 1024>>>(smask, p_idx_s, p_rnk_s, p_cnt_s, SS);
    compact_index<<<BB, 1024>>>(tmask, p_idx_t, p_rnk_t, p_cnt_t, TT);
    seq_prep<<<NCHUNK_S, 256>>>(seq, p_rnk_s, out, p_seq2);
    tgtv_prep<<<dim3(TT / 32, HH / 32, BB), dim3(32, 8)>>>(tgt, p_rnk_t, p_tgt2, p_vT2);
    zero_pad<<<dim3(BB, 3, 8), 256>>>(p_cnt_s, p_cnt_t, p_seq2, p_tgt2, p_vT2);
    split_plain<<<(HH * HH / 4 + 255) / 256, 256>>>(W, p_W2, HH, HH);
    colstat<<<(BB * HH + 255) / 256, 256>>>(tgt, tmask, p_cm, p_vm);

    // 1+2 merged) seq_t AND tgt_t = relu(X @ W^T), both compacted
    const int Y_SEQ = (BB * SS) / 128;   // 256
    const int Y_TGT = (BB * TT) / 128;   // 32
    gemm_mma<0><<<dim3(HH / 128, Y_SEQ + Y_TGT, 1), 256, SMEM_DYN>>>(
        p_seq2, p_W2, (long)SS * 2 * HH, (long)TT * 2 * HH, HH,
        nullptr, nullptr, p_seqt2, 0,
        p_tgt2, p_tgtt2, Y_SEQ, p_cnt_s, p_cnt_t, nullptr, nullptr, nullptr);

    // 3) logits = seq_t @ tgt_t^T (rows AND cols compacted)
    gemm_mma<1><<<dim3(TT / 128, SS / 128, BB), 256, SMEM_DYN>>>(
        p_seqt2, p_tgtt2, (long)SS * 2 * HH, (long)TT * 2 * HH, HH,
        p_logits, nullptr, nullptr, 0, nullptr, nullptr, 1 << 30,
        p_cnt_s, p_cnt_t, nullptr, nullptr, nullptr);

    // 4) softmax on compacted logits; emits compacted probs + c
    softmax_c<<<BB * SS, 128>>>(p_logits, p_probs2, p_c, p_cnt_s, p_cnt_t);

    // 5) attn_out = P_compact @ V_compact + c * Vm (rank-1), scatter rows
    gemm_mma<2><<<dim3(HH / 128, SS / 128, BB), 256, SMEM_DYN>>>(
        p_probs2, p_vT2, (long)SS * 2 * TT, (long)HH * 2 * TT, TT,
        out, out_attn, nullptr, write_attn, nullptr, nullptr, 1 << 30,
        p_cnt_s, p_cnt_t, p_idx_s, p_c, p_vm);

    // 6) masked seq rows: attn = colmean(V), cat second half = 0
    fill_masked<<<NCHUNK_S, 256>>>(smask, p_cm, out, out_attn, write_attn);
}